// round 1
// baseline (speedup 1.0000x reference)
#include <cuda_runtime.h>
#include <math.h>

// Problem dims (fixed by the reference)
constexpr int NB = 8;
constexpr int NT = 1024;
constexpr int NC = 1024;
constexpr int NELEM = NB * NT * NC;      // 8M
constexpr int M_GEMM = NB * NT;          // 8192

// -------- scratch (device globals; no runtime allocation allowed) --------
__device__ float g_xk[NELEM];
__device__ float g_xv[NELEM];
__device__ float g_xr[NELEM];
__device__ float g_k [NELEM];
__device__ float g_v [NELEM];
__device__ float g_r [NELEM];
// rwkv reuses g_xk after the three input GEMMs are done.

// ---------------------------------------------------------------------------
// 1) time-shift mix: xk = xx + mk*(x - xx), etc. (xx[t] = x[t-1], xx[0]=0)
// ---------------------------------------------------------------------------
__global__ void mix_kernel(const float* __restrict__ x,
                           const float* __restrict__ mk,
                           const float* __restrict__ mv,
                           const float* __restrict__ mr,
                           float* __restrict__ xk,
                           float* __restrict__ xv,
                           float* __restrict__ xr)
{
    int i = blockIdx.x * blockDim.x + threadIdx.x;   // float4 index
    const int n4 = NELEM / 4;
    if (i >= n4) return;
    const int c4 = i & (NC / 4 - 1);
    const int t  = (i / (NC / 4)) & (NT - 1);

    float4 xc = reinterpret_cast<const float4*>(x)[i];
    float4 xp = (t == 0) ? make_float4(0.f, 0.f, 0.f, 0.f)
                         : reinterpret_cast<const float4*>(x)[i - NC / 4];
    float4 k4 = reinterpret_cast<const float4*>(mk)[c4];
    float4 v4 = reinterpret_cast<const float4*>(mv)[c4];
    float4 r4 = reinterpret_cast<const float4*>(mr)[c4];

    float4 ok, ov, orr;
    ok.x = fmaf(k4.x, xc.x - xp.x, xp.x);
    ok.y = fmaf(k4.y, xc.y - xp.y, xp.y);
    ok.z = fmaf(k4.z, xc.z - xp.z, xp.z);
    ok.w = fmaf(k4.w, xc.w - xp.w, xp.w);
    ov.x = fmaf(v4.x, xc.x - xp.x, xp.x);
    ov.y = fmaf(v4.y, xc.y - xp.y, xp.y);
    ov.z = fmaf(v4.z, xc.z - xp.z, xp.z);
    ov.w = fmaf(v4.w, xc.w - xp.w, xp.w);
    orr.x = fmaf(r4.x, xc.x - xp.x, xp.x);
    orr.y = fmaf(r4.y, xc.y - xp.y, xp.y);
    orr.z = fmaf(r4.z, xc.z - xp.z, xp.z);
    orr.w = fmaf(r4.w, xc.w - xp.w, xp.w);

    reinterpret_cast<float4*>(xk)[i] = ok;
    reinterpret_cast<float4*>(xv)[i] = ov;
    reinterpret_cast<float4*>(xr)[i] = orr;
}

// ---------------------------------------------------------------------------
// 2) NT GEMM: C[m,n] = sum_k A[m,k] * W[n,k]
//    A: M x K row-major, W: N x K row-major, C: M x N row-major.
//    Classic 128x128x8 tile, 8x8 per thread, 256 threads.
//    M,N,K are multiples of 128/8 here; no bounds checks.
// ---------------------------------------------------------------------------
#define GBM 128
#define GBN 128
#define GBK 8
#define GTM 8
#define GTN 8

__global__ __launch_bounds__(256) void gemm_nt(const float* __restrict__ A,
                                               const float* __restrict__ W,
                                               float* __restrict__ Cm,
                                               int M, int N, int K)
{
    __shared__ float As[GBK][GBM];
    __shared__ float Bs[GBK][GBN];

    const int tid = threadIdx.x;
    const int bm  = blockIdx.y * GBM;
    const int bn  = blockIdx.x * GBN;
    const int tx  = tid & 15;    // 0..15
    const int ty  = tid >> 4;    // 0..15

    // load mapping: 128 rows * 2 float4 each = 256 float4
    const int ar = tid >> 1;            // 0..127
    const int ac = (tid & 1) * 4;       // 0 or 4
    const float* Ab = A + (size_t)(bm + ar) * K + ac;
    const float* Wb = W + (size_t)(bn + ar) * K + ac;

    float acc[GTM][GTN];
    #pragma unroll
    for (int i = 0; i < GTM; i++)
        #pragma unroll
        for (int j = 0; j < GTN; j++) acc[i][j] = 0.f;

    for (int k0 = 0; k0 < K; k0 += GBK) {
        float4 av = *reinterpret_cast<const float4*>(Ab + k0);
        float4 bv = *reinterpret_cast<const float4*>(Wb + k0);
        As[ac + 0][ar] = av.x;  As[ac + 1][ar] = av.y;
        As[ac + 2][ar] = av.z;  As[ac + 3][ar] = av.w;
        Bs[ac + 0][ar] = bv.x;  Bs[ac + 1][ar] = bv.y;
        Bs[ac + 2][ar] = bv.z;  Bs[ac + 3][ar] = bv.w;
        __syncthreads();

        #pragma unroll
        for (int kk = 0; kk < GBK; kk++) {
            float areg[GTM], breg[GTN];
            *reinterpret_cast<float4*>(&areg[0]) =
                *reinterpret_cast<const float4*>(&As[kk][ty * GTM + 0]);
            *reinterpret_cast<float4*>(&areg[4]) =
                *reinterpret_cast<const float4*>(&As[kk][ty * GTM + 4]);
            *reinterpret_cast<float4*>(&breg[0]) =
                *reinterpret_cast<const float4*>(&Bs[kk][tx * GTN + 0]);
            *reinterpret_cast<float4*>(&breg[4]) =
                *reinterpret_cast<const float4*>(&Bs[kk][tx * GTN + 4]);
            #pragma unroll
            for (int i = 0; i < GTM; i++)
                #pragma unroll
                for (int j = 0; j < GTN; j++)
                    acc[i][j] = fmaf(areg[i], breg[j], acc[i][j]);
        }
        __syncthreads();
    }

    #pragma unroll
    for (int i = 0; i < GTM; i++) {
        float* crow = Cm + (size_t)(bm + ty * GTM + i) * N + bn + tx * GTN;
        reinterpret_cast<float4*>(crow)[0] =
            make_float4(acc[i][0], acc[i][1], acc[i][2], acc[i][3]);
        reinterpret_cast<float4*>(crow)[1] =
            make_float4(acc[i][4], acc[i][5], acc[i][6], acc[i][7]);
    }
}

// ---------------------------------------------------------------------------
// 3) WKV scan. One thread per (b, channel). All tensors (B,T,C) row-major,
//    so the loads/stores are fully coalesced across a warp.
//      ek   = exp(min(k,60))
//      kv   = ek * v
//      wkv  = e^u * kv + A ;  wk = e^u * ek + Bacc + 1e-9
//      y    = sigmoid(r) * wkv / wk
//      A   <- p*A + kv    ;  Bacc <- p*Bacc + ek   (p = exp(-exp(decay)))
// ---------------------------------------------------------------------------
__global__ void scan_kernel(const float* __restrict__ k,
                            const float* __restrict__ v,
                            const float* __restrict__ r,
                            const float* __restrict__ td,
                            const float* __restrict__ tf,
                            float* __restrict__ y)
{
    const int c = blockIdx.x * blockDim.x + threadIdx.x;  // 0..NC-1
    const int b = blockIdx.y;
    const float ew = __expf(td[c]);
    const float p  = __expf(-ew);
    const float u  = __expf(tf[c]);

    size_t idx = (size_t)b * NT * NC + c;
    float Aacc = 0.f, Bacc = 0.f;

    #pragma unroll 4
    for (int t = 0; t < NT; t++, idx += NC) {
        const float kt = k[idx];
        const float vt = v[idx];
        const float rt = r[idx];
        const float ek = __expf(fminf(kt, 60.f));
        const float kv = ek * vt;
        const float num = fmaf(u, kv, Aacc);
        const float den = fmaf(u, ek, Bacc) + 1e-9f;
        const float sig = 1.f / (1.f + __expf(-rt));
        y[idx] = sig * num / den;
        Aacc = fmaf(p, Aacc, kv);
        Bacc = fmaf(p, Bacc, ek);
    }
}

// ---------------------------------------------------------------------------
// launch
// ---------------------------------------------------------------------------
extern "C" void kernel_launch(void* const* d_in, const int* in_sizes, int n_in,
                              void* d_out, int out_size)
{
    const float* x  = (const float*)d_in[0];
    const float* td = (const float*)d_in[1];
    const float* tf = (const float*)d_in[2];
    const float* mk = (const float*)d_in[3];
    const float* mv = (const float*)d_in[4];
    const float* mr = (const float*)d_in[5];
    const float* Wk = (const float*)d_in[6];
    const float* Wv = (const float*)d_in[7];
    const float* Wr = (const float*)d_in[8];
    const float* Wo = (const float*)d_in[9];
    float* out = (float*)d_out;

    float *xk, *xv, *xr, *kb, *vb, *rb;
    cudaGetSymbolAddress((void**)&xk, g_xk);
    cudaGetSymbolAddress((void**)&xv, g_xv);
    cudaGetSymbolAddress((void**)&xr, g_xr);
    cudaGetSymbolAddress((void**)&kb, g_k);
    cudaGetSymbolAddress((void**)&vb, g_v);
    cudaGetSymbolAddress((void**)&rb, g_r);

    // 1) mixes
    {
        int n4 = NELEM / 4;
        mix_kernel<<<(n4 + 255) / 256, 256>>>(x, mk, mv, mr, xk, xv, xr);
    }

    // 2) projections (NT GEMMs), all outputs (B,T,C) row-major
    dim3 ggrid(NC / GBN, M_GEMM / GBM);
    gemm_nt<<<ggrid, 256>>>(xk, Wk, kb, M_GEMM, NC, NC);
    gemm_nt<<<ggrid, 256>>>(xv, Wv, vb, M_GEMM, NC, NC);
    gemm_nt<<<ggrid, 256>>>(xr, Wr, rb, M_GEMM, NC, NC);

    // 3) wkv scan + sigmoid gate -> rwkv (reuse g_xk)
    scan_kernel<<<dim3(NC / 256, NB), 256>>>(kb, vb, rb, td, tf, xk);

    // 4) output projection
    gemm_nt<<<ggrid, 256>>>(xk, Wo, out, M_GEMM, NC, NC);
}

// round 4
// speedup vs baseline: 2.7399x; 2.7399x over previous
#include <cuda_runtime.h>
#include <cuda_bf16.h>
#include <cstdint>
#include <math.h>

// Problem dims (fixed)
constexpr int NB = 8;
constexpr int NT = 1024;
constexpr int NC = 1024;
constexpr int NELEM = NB * NT * NC;   // 8M
constexpr int MG = NB * NT;           // 8192 GEMM rows

// scan chunking
constexpr int SG = 16;                // chunks along T
constexpr int SL = NT / SG;           // 64 steps per chunk

// ---------------- scratch (device globals; no runtime alloc) ----------------
__device__ __nv_bfloat16 g_xkh[NELEM], g_xkl[NELEM];
__device__ __nv_bfloat16 g_xvh[NELEM], g_xvl[NELEM];
__device__ __nv_bfloat16 g_xrh[NELEM], g_xrl[NELEM];
__device__ float g_k[NELEM], g_v[NELEM], g_r[NELEM];
__device__ __nv_bfloat16 g_wh[4 * NC * NC], g_wl[4 * NC * NC];
__device__ float g_Sa[SG * NB * NC], g_Sb[SG * NB * NC];
// rwkv hi/lo reuse g_xkh / g_xkl after the three input GEMMs complete.

// ---------------- helpers ----------------
__device__ __forceinline__ uint32_t smem_u32(const void* p) {
    uint32_t a;
    asm("{ .reg .u64 t; cvta.to.shared.u64 t, %1; cvt.u32.u64 %0, t; }"
        : "=r"(a) : "l"(p));
    return a;
}
__device__ __forceinline__ void cp16(uint32_t s, const void* g) {
    asm volatile("cp.async.cg.shared.global [%0], [%1], 16;\n" :: "r"(s), "l"(g));
}
#define CP_COMMIT() asm volatile("cp.async.commit_group;\n" ::: "memory")
#define CP_WAIT2()  asm volatile("cp.async.wait_group 2;\n" ::: "memory")

__device__ __forceinline__ void ldmx4(uint32_t* r, uint32_t addr) {
    asm volatile("ldmatrix.sync.aligned.m8n8.x4.shared.b16 {%0,%1,%2,%3}, [%4];"
                 : "=r"(r[0]), "=r"(r[1]), "=r"(r[2]), "=r"(r[3]) : "r"(addr));
}
__device__ __forceinline__ void mma16816(float* c, const uint32_t* a,
                                         uint32_t b0, uint32_t b1) {
    asm volatile(
        "mma.sync.aligned.m16n8k16.row.col.f32.bf16.bf16.f32 "
        "{%0,%1,%2,%3}, {%4,%5,%6,%7}, {%8,%9}, {%0,%1,%2,%3};"
        : "+f"(c[0]), "+f"(c[1]), "+f"(c[2]), "+f"(c[3])
        : "r"(a[0]), "r"(a[1]), "r"(a[2]), "r"(a[3]), "r"(b0), "r"(b1));
}

// ---------------- bf16 split helpers ----------------
__device__ __forceinline__ unsigned pk2(float a, float b) {
    __nv_bfloat162 t = __floats2bfloat162_rn(a, b);
    return *reinterpret_cast<unsigned*>(&t);
}
__device__ __forceinline__ void store_split4(__nv_bfloat16* h, __nv_bfloat16* l,
                                             size_t i4, float a0, float a1,
                                             float a2, float a3) {
    float h0 = __bfloat162float(__float2bfloat16(a0));
    float h1 = __bfloat162float(__float2bfloat16(a1));
    float h2 = __bfloat162float(__float2bfloat16(a2));
    float h3 = __bfloat162float(__float2bfloat16(a3));
    uint2 hv = make_uint2(pk2(a0, a1), pk2(a2, a3));
    uint2 lv = make_uint2(pk2(a0 - h0, a1 - h1), pk2(a2 - h2, a3 - h3));
    reinterpret_cast<uint2*>(h)[i4] = hv;
    reinterpret_cast<uint2*>(l)[i4] = lv;
}

// ---------------------------------------------------------------------------
// weight split: fp32 [N,K] -> bf16 hi/lo
// ---------------------------------------------------------------------------
__global__ void wsplit_kernel(const float* __restrict__ W,
                              __nv_bfloat16* __restrict__ h,
                              __nv_bfloat16* __restrict__ l) {
    int i = blockIdx.x * blockDim.x + threadIdx.x;     // float4 idx
    if (i >= NC * NC / 4) return;
    float4 w = reinterpret_cast<const float4*>(W)[i];
    store_split4(h, l, i, w.x, w.y, w.z, w.w);
}

// ---------------------------------------------------------------------------
// fused time-shift mix + bf16 split (xk, xv, xr hi/lo)
// ---------------------------------------------------------------------------
__global__ void mix_split_kernel(const float* __restrict__ x,
                                 const float* __restrict__ mk,
                                 const float* __restrict__ mv,
                                 const float* __restrict__ mr,
                                 __nv_bfloat16* __restrict__ xkh, __nv_bfloat16* __restrict__ xkl,
                                 __nv_bfloat16* __restrict__ xvh, __nv_bfloat16* __restrict__ xvl,
                                 __nv_bfloat16* __restrict__ xrh, __nv_bfloat16* __restrict__ xrl) {
    int i = blockIdx.x * blockDim.x + threadIdx.x;     // float4 idx
    if (i >= NELEM / 4) return;
    const int c4 = i & (NC / 4 - 1);
    const int t  = (i >> 8) & (NT - 1);

    float4 xc = reinterpret_cast<const float4*>(x)[i];
    float4 xp = (t == 0) ? make_float4(0.f, 0.f, 0.f, 0.f)
                         : reinterpret_cast<const float4*>(x)[i - NC / 4];
    float4 k4 = reinterpret_cast<const float4*>(mk)[c4];
    float4 v4 = reinterpret_cast<const float4*>(mv)[c4];
    float4 r4 = reinterpret_cast<const float4*>(mr)[c4];

    float dx0 = xc.x - xp.x, dx1 = xc.y - xp.y, dx2 = xc.z - xp.z, dx3 = xc.w - xp.w;

    store_split4(xkh, xkl, i, fmaf(k4.x, dx0, xp.x), fmaf(k4.y, dx1, xp.y),
                              fmaf(k4.z, dx2, xp.z), fmaf(k4.w, dx3, xp.w));
    store_split4(xvh, xvl, i, fmaf(v4.x, dx0, xp.x), fmaf(v4.y, dx1, xp.y),
                              fmaf(v4.z, dx2, xp.z), fmaf(v4.w, dx3, xp.w));
    store_split4(xrh, xrl, i, fmaf(r4.x, dx0, xp.x), fmaf(r4.y, dx1, xp.y),
                              fmaf(r4.z, dx2, xp.z), fmaf(r4.w, dx3, xp.w));
}

// ---------------------------------------------------------------------------
// mma.sync bf16x3 GEMM: C[m,n] = sum_k (Ah+Al)[m,k] * (Wh+Wl)[n,k]
// (drops Al*Wl term; error ~2^-17)
// CTA tile 128x128x32, 8 warps (64x32 each), 3-stage cp.async pipeline.
// ---------------------------------------------------------------------------
constexpr int LDT = 40;                    // padded smem row stride (bf16 elems)
constexpr int TILE_ELE = 128 * LDT;        // 5120 elems / 10240 B
constexpr int STAGE_ELE = 4 * TILE_ELE;    // Ah, Al, Wh, Wl
constexpr int NSTAGE = 3;
constexpr int GEMM_SMEM = NSTAGE * STAGE_ELE * 2;   // 122880 B
constexpr int KCH = NC / 32;               // 32 chunks

__global__ void __launch_bounds__(256)
gemm3x_kernel(const __nv_bfloat16* __restrict__ Ah, const __nv_bfloat16* __restrict__ Al,
              const __nv_bfloat16* __restrict__ Wh, const __nv_bfloat16* __restrict__ Wl,
              float* __restrict__ C) {
    extern __shared__ __nv_bfloat16 smem[];
    const uint32_t sb = smem_u32(smem);
    const int tid = threadIdx.x;
    const int lane = tid & 31;
    const int wid = tid >> 5;
    const int wm = wid & 1;          // 0..1 (M dir, 64 rows)
    const int wn = wid >> 1;         // 0..3 (N dir, 32 cols)
    const int nTile = blockIdx.x, mTile = blockIdx.y;

    const char* gbase[4];
    gbase[0] = (const char*)(Ah + (size_t)mTile * 128 * NC);
    gbase[1] = (const char*)(Al + (size_t)mTile * 128 * NC);
    gbase[2] = (const char*)(Wh + (size_t)nTile * 128 * NC);
    gbase[3] = (const char*)(Wl + (size_t)nTile * 128 * NC);

    // loader mapping: per tile, 512 x 16B; u = i*256 + tid -> row=u>>2, col=(u&3)*8
    auto load_chunk = [&](int c, int s) {
        uint32_t st = sb + (uint32_t)s * STAGE_ELE * 2;
        #pragma unroll
        for (int t = 0; t < 4; t++) {
            #pragma unroll
            for (int i = 0; i < 2; i++) {
                int u = i * 256 + tid;
                int row = u >> 2, col = (u & 3) * 8;
                cp16(st + (uint32_t)t * TILE_ELE * 2 + (uint32_t)(row * LDT + col) * 2,
                     gbase[t] + (size_t)row * 2048 + (size_t)(c * 32 + col) * 2);
            }
        }
        CP_COMMIT();
    };

    load_chunk(0, 0);
    load_chunk(1, 1);
    load_chunk(2, 2);

    float acc[4][4][4];
    #pragma unroll
    for (int mt = 0; mt < 4; mt++)
        #pragma unroll
        for (int nt = 0; nt < 4; nt++)
            #pragma unroll
            for (int q = 0; q < 4; q++) acc[mt][nt][q] = 0.f;

    // ldmatrix per-lane offsets (elems): row = (lane&15), col-sel = (lane>>4)*8
    const int lrow = lane & 15;
    const int lcol = (lane >> 4) * 8;

    for (int c = 0; c < KCH; c++) {
        const int s = c % NSTAGE;
        CP_WAIT2();
        __syncthreads();
        const uint32_t st = sb + (uint32_t)s * STAGE_ELE * 2;
        const uint32_t sAh = st;
        const uint32_t sAl = st + TILE_ELE * 2;
        const uint32_t sWh = st + 2 * TILE_ELE * 2;
        const uint32_t sWl = st + 3 * TILE_ELE * 2;

        #pragma unroll
        for (int ks = 0; ks < 2; ks++) {
            const int kc = ks * 16 + lcol;
            uint32_t ah[4][4], al[4][4], bh[2][4], bl[2][4];
            #pragma unroll
            for (int mt = 0; mt < 4; mt++) {
                uint32_t ro = (uint32_t)((wm * 64 + mt * 16 + lrow) * LDT + kc) * 2;
                ldmx4(ah[mt], sAh + ro);
                ldmx4(al[mt], sAl + ro);
            }
            #pragma unroll
            for (int pr = 0; pr < 2; pr++) {
                uint32_t ro = (uint32_t)((wn * 32 + pr * 16 + lrow) * LDT + kc) * 2;
                ldmx4(bh[pr], sWh + ro);
                ldmx4(bl[pr], sWl + ro);
            }
            // b-frag for n-tile nt: pair = nt>>1, idx = nt&1 -> {r[idx], r[idx+2]}
            #pragma unroll
            for (int mt = 0; mt < 4; mt++)
                #pragma unroll
                for (int nt = 0; nt < 4; nt++) {
                    const int pr = nt >> 1, ix = nt & 1;
                    mma16816(acc[mt][nt], ah[mt], bh[pr][ix], bh[pr][ix + 2]);
                    mma16816(acc[mt][nt], ah[mt], bl[pr][ix], bl[pr][ix + 2]);
                    mma16816(acc[mt][nt], al[mt], bh[pr][ix], bh[pr][ix + 2]);
                }
        }
        __syncthreads();
        if (c + NSTAGE < KCH) load_chunk(c + NSTAGE, s);
        else CP_COMMIT();
    }

    // epilogue
    const int erow = mTile * 128 + wm * 64 + (lane >> 2);
    const int ecol = nTile * 128 + wn * 32 + (lane & 3) * 2;
    #pragma unroll
    for (int mt = 0; mt < 4; mt++) {
        #pragma unroll
        for (int nt = 0; nt < 4; nt++) {
            float* p0 = C + (size_t)(erow + mt * 16) * NC + ecol + nt * 8;
            float* p1 = C + (size_t)(erow + mt * 16 + 8) * NC + ecol + nt * 8;
            *reinterpret_cast<float2*>(p0) = make_float2(acc[mt][nt][0], acc[mt][nt][1]);
            *reinterpret_cast<float2*>(p1) = make_float2(acc[mt][nt][2], acc[mt][nt][3]);
        }
    }
}

// ---------------------------------------------------------------------------
// chunk-parallel WKV scan (3 passes)
// ---------------------------------------------------------------------------
__global__ void scan_p1(const float* __restrict__ k, const float* __restrict__ v,
                        const float* __restrict__ td,
                        float* __restrict__ Sa, float* __restrict__ Sb) {
    const int c = blockIdx.x * blockDim.x + threadIdx.x;
    const int b = blockIdx.y, g = blockIdx.z;
    const float p = __expf(-__expf(td[c]));
    size_t idx = ((size_t)b * NT + g * SL) * NC + c;
    float A = 0.f, Bb = 0.f;
    #pragma unroll 4
    for (int t = 0; t < SL; t++, idx += NC) {
        float ek = __expf(fminf(k[idx], 60.f));
        float kv = ek * v[idx];
        A  = fmaf(p, A, kv);
        Bb = fmaf(p, Bb, ek);
    }
    size_t o = ((size_t)g * NB + b) * NC + c;
    Sa[o] = A; Sb[o] = Bb;
}

__global__ void scan_p2(const float* __restrict__ td,
                        float* __restrict__ Sa, float* __restrict__ Sb) {
    const int c = blockIdx.x * blockDim.x + threadIdx.x;
    const int b = blockIdx.y;
    const float pl = __expf(-__expf(td[c]) * (float)SL);   // p^SL (underflows to 0 ok)
    float A = 0.f, Bb = 0.f;
    for (int g = 0; g < SG; g++) {
        size_t o = ((size_t)g * NB + b) * NC + c;
        float ta = Sa[o], tb = Sb[o];
        Sa[o] = A; Sb[o] = Bb;                 // start state for chunk g
        A  = fmaf(pl, A, ta);
        Bb = fmaf(pl, Bb, tb);
    }
}

__global__ void scan_p3(const float* __restrict__ k, const float* __restrict__ v,
                        const float* __restrict__ r, const float* __restrict__ td,
                        const float* __restrict__ tf,
                        const float* __restrict__ Sa, const float* __restrict__ Sb,
                        __nv_bfloat16* __restrict__ yh, __nv_bfloat16* __restrict__ yl) {
    const int c = blockIdx.x * blockDim.x + threadIdx.x;
    const int b = blockIdx.y, g = blockIdx.z;
    const float p = __expf(-__expf(td[c]));
    const float u = __expf(tf[c]);
    size_t o = ((size_t)g * NB + b) * NC + c;
    float A = Sa[o], Bb = Sb[o];
    size_t idx = ((size_t)b * NT + g * SL) * NC + c;
    #pragma unroll 2
    for (int t = 0; t < SL; t++, idx += NC) {
        float ek = __expf(fminf(k[idx], 60.f));
        float kv = ek * v[idx];
        float num = fmaf(u, kv, A);
        float den = fmaf(u, ek, Bb) + 1e-9f;
        float sig = 1.f / (1.f + __expf(-r[idx]));
        float y = sig * num / den;
        __nv_bfloat16 hi = __float2bfloat16(y);
        yh[idx] = hi;
        yl[idx] = __float2bfloat16(y - __bfloat162float(hi));
        A  = fmaf(p, A, kv);
        Bb = fmaf(p, Bb, ek);
    }
}

// ---------------------------------------------------------------------------
// launch
// ---------------------------------------------------------------------------
extern "C" void kernel_launch(void* const* d_in, const int* in_sizes, int n_in,
                              void* d_out, int out_size) {
    const float* x  = (const float*)d_in[0];
    const float* td = (const float*)d_in[1];
    const float* tf = (const float*)d_in[2];
    const float* mk = (const float*)d_in[3];
    const float* mv = (const float*)d_in[4];
    const float* mr = (const float*)d_in[5];
    const float* Wk = (const float*)d_in[6];
    const float* Wv = (const float*)d_in[7];
    const float* Wr = (const float*)d_in[8];
    const float* Wo = (const float*)d_in[9];
    float* out = (float*)d_out;

    __nv_bfloat16 *xkh, *xkl, *xvh, *xvl, *xrh, *xrl, *wh, *wl;
    float *kb, *vb, *rb, *Sa, *Sb;
    cudaGetSymbolAddress((void**)&xkh, g_xkh); cudaGetSymbolAddress((void**)&xkl, g_xkl);
    cudaGetSymbolAddress((void**)&xvh, g_xvh); cudaGetSymbolAddress((void**)&xvl, g_xvl);
    cudaGetSymbolAddress((void**)&xrh, g_xrh); cudaGetSymbolAddress((void**)&xrl, g_xrl);
    cudaGetSymbolAddress((void**)&wh, g_wh);   cudaGetSymbolAddress((void**)&wl, g_wl);
    cudaGetSymbolAddress((void**)&kb, g_k);    cudaGetSymbolAddress((void**)&vb, g_v);
    cudaGetSymbolAddress((void**)&rb, g_r);
    cudaGetSymbolAddress((void**)&Sa, g_Sa);   cudaGetSymbolAddress((void**)&Sb, g_Sb);

    cudaFuncSetAttribute(gemm3x_kernel,
                         cudaFuncAttributeMaxDynamicSharedMemorySize, GEMM_SMEM);

    const size_t WN = (size_t)NC * NC;
    // 1) weight splits
    wsplit_kernel<<<WN / 4 / 256, 256>>>(Wk, wh + 0 * WN, wl + 0 * WN);
    wsplit_kernel<<<WN / 4 / 256, 256>>>(Wv, wh + 1 * WN, wl + 1 * WN);
    wsplit_kernel<<<WN / 4 / 256, 256>>>(Wr, wh + 2 * WN, wl + 2 * WN);
    wsplit_kernel<<<WN / 4 / 256, 256>>>(Wo, wh + 3 * WN, wl + 3 * WN);

    // 2) fused time-shift mix + split
    mix_split_kernel<<<NELEM / 4 / 256, 256>>>(x, mk, mv, mr,
                                               xkh, xkl, xvh, xvl, xrh, xrl);

    // 3) k/v/r projections (mma.sync bf16x3)
    dim3 gg(NC / 128, MG / 128);   // (8, 64)
    gemm3x_kernel<<<gg, 256, GEMM_SMEM>>>(xkh, xkl, wh + 0 * WN, wl + 0 * WN, kb);
    gemm3x_kernel<<<gg, 256, GEMM_SMEM>>>(xvh, xvl, wh + 1 * WN, wl + 1 * WN, vb);
    gemm3x_kernel<<<gg, 256, GEMM_SMEM>>>(xrh, xrl, wh + 2 * WN, wl + 2 * WN, rb);

    // 4) chunk-parallel WKV scan; outputs rwkv hi/lo into xkh/xkl (reuse)
    scan_p1<<<dim3(NC / 256, NB, SG), 256>>>(kb, vb, td, Sa, Sb);
    scan_p2<<<dim3(NC / 256, NB), 256>>>(td, Sa, Sb);
    scan_p3<<<dim3(NC / 256, NB, SG), 256>>>(kb, vb, rb, td, tf, Sa, Sb, xkh, xkl);

    // 5) output projection
    gemm3x_kernel<<<gg, 256, GEMM_SMEM>>>(xkh, xkl, wh + 3 * WN, wl + 3 * WN, out);
}

// round 5
// speedup vs baseline: 3.8981x; 1.4227x over previous
#include <cuda_runtime.h>
#include <cuda_fp16.h>
#include <cstdint>
#include <math.h>

// Problem dims (fixed)
constexpr int NB = 8;
constexpr int NT = 1024;
constexpr int NC = 1024;
constexpr int NELEM = NB * NT * NC;   // 8M
constexpr int MG = NB * NT;           // 8192 GEMM rows

// scan chunking
constexpr int SG = 16;                // chunks along T
constexpr int SL = NT / SG;           // 64 steps per chunk

// ---------------- scratch (device globals; no runtime alloc) ----------------
__device__ __half g_xkh[NELEM], g_xkl[NELEM];
__device__ __half g_xvh[NELEM], g_xvl[NELEM];
__device__ __half g_xr[NELEM];
__device__ float g_k[NELEM], g_v[NELEM], g_r[NELEM];
__device__ __half g_w[5 * NC * NC];   // [wk_h, wk_l, wv, wr, wo]
__device__ float g_Sa[SG * NB * NC], g_Sb[SG * NB * NC];
// rwkv hi/lo reuse g_xkh / g_xkl after the k/v GEMMs complete.

// ---------------- helpers ----------------
__device__ __forceinline__ uint32_t smem_u32(const void* p) {
    uint32_t a;
    asm("{ .reg .u64 t; cvta.to.shared.u64 t, %1; cvt.u32.u64 %0, t; }"
        : "=r"(a) : "l"(p));
    return a;
}
__device__ __forceinline__ void cp16(uint32_t s, const void* g) {
    asm volatile("cp.async.cg.shared.global [%0], [%1], 16;\n" :: "r"(s), "l"(g));
}
#define CP_COMMIT() asm volatile("cp.async.commit_group;\n" ::: "memory")
#define CP_WAIT1()  asm volatile("cp.async.wait_group 1;\n" ::: "memory")

__device__ __forceinline__ void ldmx4(uint32_t* r, uint32_t addr) {
    asm volatile("ldmatrix.sync.aligned.m8n8.x4.shared.b16 {%0,%1,%2,%3}, [%4];"
                 : "=r"(r[0]), "=r"(r[1]), "=r"(r[2]), "=r"(r[3]) : "r"(addr));
}
__device__ __forceinline__ void mma16816(float* c, const uint32_t* a,
                                         uint32_t b0, uint32_t b1) {
    asm volatile(
        "mma.sync.aligned.m16n8k16.row.col.f32.f16.f16.f32 "
        "{%0,%1,%2,%3}, {%4,%5,%6,%7}, {%8,%9}, {%0,%1,%2,%3};"
        : "+f"(c[0]), "+f"(c[1]), "+f"(c[2]), "+f"(c[3])
        : "r"(a[0]), "r"(a[1]), "r"(a[2]), "r"(a[3]), "r"(b0), "r"(b1));
}

// ---------------- fp16 split helpers ----------------
__device__ __forceinline__ unsigned pk2h(float a, float b) {
    __half2 t = __floats2half2_rn(a, b);
    return *reinterpret_cast<unsigned*>(&t);
}
__device__ __forceinline__ void store_split4h(__half* h, __half* l, size_t i4,
                                              float a0, float a1, float a2, float a3) {
    float h0 = __half2float(__float2half_rn(a0));
    float h1 = __half2float(__float2half_rn(a1));
    float h2 = __half2float(__float2half_rn(a2));
    float h3 = __half2float(__float2half_rn(a3));
    reinterpret_cast<uint2*>(h)[i4] = make_uint2(pk2h(a0, a1), pk2h(a2, a3));
    reinterpret_cast<uint2*>(l)[i4] =
        make_uint2(pk2h(a0 - h0, a1 - h1), pk2h(a2 - h2, a3 - h3));
}
__device__ __forceinline__ void store_cast4h(__half* h, size_t i4,
                                             float a0, float a1, float a2, float a3) {
    reinterpret_cast<uint2*>(h)[i4] = make_uint2(pk2h(a0, a1), pk2h(a2, a3));
}

// ---------------------------------------------------------------------------
// weight prep: split (hi/lo fp16) for Wk, plain cast for Wv/Wr/Wo
// ---------------------------------------------------------------------------
__global__ void wsplit_kernel(const float* __restrict__ W,
                              __half* __restrict__ h, __half* __restrict__ l) {
    int i = blockIdx.x * blockDim.x + threadIdx.x;
    if (i >= NC * NC / 4) return;
    float4 w = reinterpret_cast<const float4*>(W)[i];
    store_split4h(h, l, i, w.x, w.y, w.z, w.w);
}
__global__ void wcast_kernel(const float* __restrict__ W, __half* __restrict__ h) {
    int i = blockIdx.x * blockDim.x + threadIdx.x;
    if (i >= NC * NC / 4) return;
    float4 w = reinterpret_cast<const float4*>(W)[i];
    store_cast4h(h, i, w.x, w.y, w.z, w.w);
}

// ---------------------------------------------------------------------------
// fused time-shift mix: xk (hi/lo), xv (hi/lo), xr (single fp16)
// ---------------------------------------------------------------------------
__global__ void mix_split_kernel(const float* __restrict__ x,
                                 const float* __restrict__ mk,
                                 const float* __restrict__ mv,
                                 const float* __restrict__ mr,
                                 __half* __restrict__ xkh, __half* __restrict__ xkl,
                                 __half* __restrict__ xvh, __half* __restrict__ xvl,
                                 __half* __restrict__ xr) {
    int i = blockIdx.x * blockDim.x + threadIdx.x;     // float4 idx
    if (i >= NELEM / 4) return;
    const int c4 = i & (NC / 4 - 1);
    const int t  = (i >> 8) & (NT - 1);

    float4 xc = reinterpret_cast<const float4*>(x)[i];
    float4 xp = (t == 0) ? make_float4(0.f, 0.f, 0.f, 0.f)
                         : reinterpret_cast<const float4*>(x)[i - NC / 4];
    float4 k4 = reinterpret_cast<const float4*>(mk)[c4];
    float4 v4 = reinterpret_cast<const float4*>(mv)[c4];
    float4 r4 = reinterpret_cast<const float4*>(mr)[c4];

    float dx0 = xc.x - xp.x, dx1 = xc.y - xp.y, dx2 = xc.z - xp.z, dx3 = xc.w - xp.w;

    store_split4h(xkh, xkl, i, fmaf(k4.x, dx0, xp.x), fmaf(k4.y, dx1, xp.y),
                               fmaf(k4.z, dx2, xp.z), fmaf(k4.w, dx3, xp.w));
    store_split4h(xvh, xvl, i, fmaf(v4.x, dx0, xp.x), fmaf(v4.y, dx1, xp.y),
                               fmaf(v4.z, dx2, xp.z), fmaf(v4.w, dx3, xp.w));
    store_cast4h(xr, i, fmaf(r4.x, dx0, xp.x), fmaf(r4.y, dx1, xp.y),
                        fmaf(r4.z, dx2, xp.z), fmaf(r4.w, dx3, xp.w));
}

// ---------------------------------------------------------------------------
// mma.sync fp16 GEMM, templated pass config.
// C[m,n] = sum_k A[m,k]*W[n,k] with A = A0(+A1), W = W0(+W1); computes
// A0W0 (+A1W0 if TA==2) (+A0W1 if TW==2), all into one fp32 accumulator.
// CTA tile 128x128x32, 8 warps (64x32 each), 3-stage cp.async pipeline,
// next-chunk loads issued BEFORE compute (single barrier per chunk).
// ---------------------------------------------------------------------------
constexpr int LDT = 40;                    // padded smem row stride (halves)
constexpr int TILE_ELE = 128 * LDT;        // 5120 elems = 10240 B
constexpr int NSTAGE = 3;
constexpr int KCH = NC / 32;               // 32 chunks

template<int TA, int TW>
__global__ void __launch_bounds__(256)
gemm_mma(const __half* __restrict__ A0, const __half* __restrict__ A1,
         const __half* __restrict__ W0, const __half* __restrict__ W1,
         float* __restrict__ C) {
    constexpr int T = TA + TW;
    constexpr int STAGE_B = T * TILE_ELE * 2;
    extern __shared__ __half smem[];
    const uint32_t sb = smem_u32(smem);
    const int tid = threadIdx.x;
    const int lane = tid & 31;
    const int wid = tid >> 5;
    const int wm = wid & 1;          // 0..1 (M dir, 64 rows)
    const int wn = wid >> 1;         // 0..3 (N dir, 32 cols)
    const int nTile = blockIdx.x, mTile = blockIdx.y;

    const char* gbase[T];
    gbase[0] = (const char*)(A0 + (size_t)mTile * 128 * NC);
    if (TA == 2) gbase[1] = (const char*)(A1 + (size_t)mTile * 128 * NC);
    gbase[TA] = (const char*)(W0 + (size_t)nTile * 128 * NC);
    if (TW == 2) gbase[TA + 1] = (const char*)(W1 + (size_t)nTile * 128 * NC);

    // loader: per tile 512 x 16B; u = i*256 + tid -> row=u>>2, col=(u&3)*8
    auto load_chunk = [&](int c, int s) {
        uint32_t st = sb + (uint32_t)s * STAGE_B;
        #pragma unroll
        for (int t = 0; t < T; t++) {
            #pragma unroll
            for (int i = 0; i < 2; i++) {
                int u = i * 256 + tid;
                int row = u >> 2, col = (u & 3) * 8;
                cp16(st + (uint32_t)t * TILE_ELE * 2 + (uint32_t)(row * LDT + col) * 2,
                     gbase[t] + (size_t)row * 2048 + (size_t)(c * 32 + col) * 2);
            }
        }
        CP_COMMIT();
    };

    load_chunk(0, 0);
    load_chunk(1, 1);

    float acc[4][4][4];
    #pragma unroll
    for (int mt = 0; mt < 4; mt++)
        #pragma unroll
        for (int nt = 0; nt < 4; nt++)
            #pragma unroll
            for (int q = 0; q < 4; q++) acc[mt][nt][q] = 0.f;

    const int lrow = lane & 15;
    const int lcol = (lane >> 4) * 8;

    for (int c = 0; c < KCH; c++) {
        const int s = c % NSTAGE;
        CP_WAIT1();
        __syncthreads();
        // issue next-next chunk into the stage freed by chunk c-1
        if (c + 2 < KCH) load_chunk(c + 2, (c + 2) % NSTAGE);
        else CP_COMMIT();

        const uint32_t st = sb + (uint32_t)s * STAGE_B;
        #pragma unroll
        for (int ks = 0; ks < 2; ks++) {
            const int kc = ks * 16 + lcol;
            uint32_t a[TA][4][4], b[TW][2][4];
            #pragma unroll
            for (int ta = 0; ta < TA; ta++)
                #pragma unroll
                for (int mt = 0; mt < 4; mt++) {
                    uint32_t ro = (uint32_t)((wm * 64 + mt * 16 + lrow) * LDT + kc) * 2;
                    ldmx4(a[ta][mt], st + (uint32_t)ta * TILE_ELE * 2 + ro);
                }
            #pragma unroll
            for (int tw = 0; tw < TW; tw++)
                #pragma unroll
                for (int pr = 0; pr < 2; pr++) {
                    uint32_t ro = (uint32_t)((wn * 32 + pr * 16 + lrow) * LDT + kc) * 2;
                    ldmx4(b[tw][pr], st + (uint32_t)(TA + tw) * TILE_ELE * 2 + ro);
                }
            #pragma unroll
            for (int mt = 0; mt < 4; mt++)
                #pragma unroll
                for (int nt = 0; nt < 4; nt++) {
                    const int pr = nt >> 1, ix = nt & 1;
                    mma16816(acc[mt][nt], a[0][mt], b[0][pr][ix], b[0][pr][ix + 2]);
                    if (TA == 2)
                        mma16816(acc[mt][nt], a[1][mt], b[0][pr][ix], b[0][pr][ix + 2]);
                    if (TW == 2)
                        mma16816(acc[mt][nt], a[0][mt], b[1][pr][ix], b[1][pr][ix + 2]);
                }
        }
        __syncthreads();   // all warps done reading stage s before it is refilled
    }

    // epilogue
    const int erow = mTile * 128 + wm * 64 + (lane >> 2);
    const int ecol = nTile * 128 + wn * 32 + (lane & 3) * 2;
    #pragma unroll
    for (int mt = 0; mt < 4; mt++) {
        #pragma unroll
        for (int nt = 0; nt < 4; nt++) {
            float* p0 = C + (size_t)(erow + mt * 16) * NC + ecol + nt * 8;
            float* p1 = C + (size_t)(erow + mt * 16 + 8) * NC + ecol + nt * 8;
            *reinterpret_cast<float2*>(p0) = make_float2(acc[mt][nt][0], acc[mt][nt][1]);
            *reinterpret_cast<float2*>(p1) = make_float2(acc[mt][nt][2], acc[mt][nt][3]);
        }
    }
}

// ---------------------------------------------------------------------------
// chunk-parallel WKV scan (3 passes)
// ---------------------------------------------------------------------------
__global__ void scan_p1(const float* __restrict__ k, const float* __restrict__ v,
                        const float* __restrict__ td,
                        float* __restrict__ Sa, float* __restrict__ Sb) {
    const int c = blockIdx.x * blockDim.x + threadIdx.x;
    const int b = blockIdx.y, g = blockIdx.z;
    const float p = __expf(-__expf(td[c]));
    size_t idx = ((size_t)b * NT + g * SL) * NC + c;
    float A = 0.f, Bb = 0.f;
    #pragma unroll 4
    for (int t = 0; t < SL; t++, idx += NC) {
        float ek = __expf(fminf(k[idx], 60.f));
        float kv = ek * v[idx];
        A  = fmaf(p, A, kv);
        Bb = fmaf(p, Bb, ek);
    }
    size_t o = ((size_t)g * NB + b) * NC + c;
    Sa[o] = A; Sb[o] = Bb;
}

__global__ void scan_p2(const float* __restrict__ td,
                        float* __restrict__ Sa, float* __restrict__ Sb) {
    const int c = blockIdx.x * blockDim.x + threadIdx.x;
    const int b = blockIdx.y;
    const float pl = __expf(-__expf(td[c]) * (float)SL);   // p^SL
    float A = 0.f, Bb = 0.f;
    for (int g = 0; g < SG; g++) {
        size_t o = ((size_t)g * NB + b) * NC + c;
        float ta = Sa[o], tb = Sb[o];
        Sa[o] = A; Sb[o] = Bb;                 // start state for chunk g
        A  = fmaf(pl, A, ta);
        Bb = fmaf(pl, Bb, tb);
    }
}

__global__ void scan_p3(const float* __restrict__ k, const float* __restrict__ v,
                        const float* __restrict__ r, const float* __restrict__ td,
                        const float* __restrict__ tf,
                        const float* __restrict__ Sa, const float* __restrict__ Sb,
                        __half* __restrict__ yh, __half* __restrict__ yl) {
    const int c = blockIdx.x * blockDim.x + threadIdx.x;
    const int b = blockIdx.y, g = blockIdx.z;
    const float p = __expf(-__expf(td[c]));
    const float u = __expf(tf[c]);
    size_t o = ((size_t)g * NB + b) * NC + c;
    float A = Sa[o], Bb = Sb[o];
    size_t idx = ((size_t)b * NT + g * SL) * NC + c;
    #pragma unroll 2
    for (int t = 0; t < SL; t++, idx += NC) {
        float ek = __expf(fminf(k[idx], 60.f));
        float kv = ek * v[idx];
        float num = fmaf(u, kv, A);
        float den = fmaf(u, ek, Bb) + 1e-9f;
        float sig = 1.f / (1.f + __expf(-r[idx]));
        float y = sig * num / den;
        __half hi = __float2half_rn(y);
        yh[idx] = hi;
        yl[idx] = __float2half_rn(y - __half2float(hi));
        A  = fmaf(p, A, kv);
        Bb = fmaf(p, Bb, ek);
    }
}

// ---------------------------------------------------------------------------
// launch
// ---------------------------------------------------------------------------
extern "C" void kernel_launch(void* const* d_in, const int* in_sizes, int n_in,
                              void* d_out, int out_size) {
    const float* x  = (const float*)d_in[0];
    const float* td = (const float*)d_in[1];
    const float* tf = (const float*)d_in[2];
    const float* mk = (const float*)d_in[3];
    const float* mv = (const float*)d_in[4];
    const float* mr = (const float*)d_in[5];
    const float* Wk = (const float*)d_in[6];
    const float* Wv = (const float*)d_in[7];
    const float* Wr = (const float*)d_in[8];
    const float* Wo = (const float*)d_in[9];
    float* out = (float*)d_out;

    __half *xkh, *xkl, *xvh, *xvl, *xr, *w;
    float *kb, *vb, *rb, *Sa, *Sb;
    cudaGetSymbolAddress((void**)&xkh, g_xkh); cudaGetSymbolAddress((void**)&xkl, g_xkl);
    cudaGetSymbolAddress((void**)&xvh, g_xvh); cudaGetSymbolAddress((void**)&xvl, g_xvl);
    cudaGetSymbolAddress((void**)&xr, g_xr);   cudaGetSymbolAddress((void**)&w, g_w);
    cudaGetSymbolAddress((void**)&kb, g_k);    cudaGetSymbolAddress((void**)&vb, g_v);
    cudaGetSymbolAddress((void**)&rb, g_r);
    cudaGetSymbolAddress((void**)&Sa, g_Sa);   cudaGetSymbolAddress((void**)&Sb, g_Sb);

    const size_t WN = (size_t)NC * NC;
    __half* wk_h = w + 0 * WN;
    __half* wk_l = w + 1 * WN;
    __half* wv   = w + 2 * WN;
    __half* wr   = w + 3 * WN;
    __half* wo   = w + 4 * WN;

    constexpr int SM4 = NSTAGE * 4 * TILE_ELE * 2;   // 122880
    constexpr int SM3 = NSTAGE * 3 * TILE_ELE * 2;   // 92160
    constexpr int SM2 = NSTAGE * 2 * TILE_ELE * 2;   // 61440
    cudaFuncSetAttribute(gemm_mma<2, 2>, cudaFuncAttributeMaxDynamicSharedMemorySize, SM4);
    cudaFuncSetAttribute(gemm_mma<2, 1>, cudaFuncAttributeMaxDynamicSharedMemorySize, SM3);
    cudaFuncSetAttribute(gemm_mma<1, 1>, cudaFuncAttributeMaxDynamicSharedMemorySize, SM2);

    // 1) weight prep
    wsplit_kernel<<<WN / 4 / 256, 256>>>(Wk, wk_h, wk_l);
    wcast_kernel<<<WN / 4 / 256, 256>>>(Wv, wv);
    wcast_kernel<<<WN / 4 / 256, 256>>>(Wr, wr);
    wcast_kernel<<<WN / 4 / 256, 256>>>(Wo, wo);

    // 2) fused time-shift mix + fp16 split/cast
    mix_split_kernel<<<NELEM / 4 / 256, 256>>>(x, mk, mv, mr, xkh, xkl, xvh, xvl, xr);

    // 3) projections
    dim3 gg(NC / 128, MG / 128);   // (8, 64)
    gemm_mma<2, 2><<<gg, 256, SM4>>>(xkh, xkl, wk_h, wk_l, kb);   // k: 3 passes
    gemm_mma<2, 1><<<gg, 256, SM3>>>(xvh, xvl, wv, nullptr, vb);  // v: 2 passes
    gemm_mma<1, 1><<<gg, 256, SM2>>>(xr, nullptr, wr, nullptr, rb); // r: 1 pass

    // 4) chunk-parallel WKV scan; rwkv hi/lo into xkh/xkl (reuse)
    scan_p1<<<dim3(NC / 256, NB, SG), 256>>>(kb, vb, td, Sa, Sb);
    scan_p2<<<dim3(NC / 256, NB), 256>>>(td, Sa, Sb);
    scan_p3<<<dim3(NC / 256, NB, SG), 256>>>(kb, vb, rb, td, tf, Sa, Sb, xkh, xkl);

    // 5) output projection: 2 passes
    gemm_mma<2, 1><<<gg, 256, SM3>>>(xkh, xkl, wo, nullptr, out);
}

// round 8
// speedup vs baseline: 4.9920x; 1.2806x over previous
#include <cuda_runtime.h>
#include <cuda_fp16.h>
#include <cstdint>
#include <math.h>

// Problem dims (fixed)
constexpr int NB = 8;
constexpr int NT = 1024;
constexpr int NC = 1024;
constexpr int NELEM = NB * NT * NC;   // 8M
constexpr int MG = NB * NT;           // 8192 GEMM rows
constexpr int WN = NC * NC;

// scan chunking
constexpr int SG = 16;                // chunks along T
constexpr int SL = NT / SG;           // 64 steps per chunk

// ---------------- scratch (device globals; no runtime alloc) ----------------
__device__ __half g_x3[3 * NELEM];    // xk | xv | xr  (slice 0 reused for rwkv y)
__device__ __half g_kvr[3 * NELEM];   // k | v | r
__device__ __half g_w[4 * WN];        // wk | wv | wr | wo
__device__ float g_Sa[SG * NB * NC], g_Sb[SG * NB * NC];

// ---------------- helpers ----------------
__device__ __forceinline__ uint32_t smem_u32(const void* p) {
    uint32_t a;
    asm("{ .reg .u64 t; cvta.to.shared.u64 t, %1; cvt.u32.u64 %0, t; }"
        : "=r"(a) : "l"(p));
    return a;
}
__device__ __forceinline__ void cp16(uint32_t s, const void* g) {
    asm volatile("cp.async.cg.shared.global [%0], [%1], 16;\n" :: "r"(s), "l"(g));
}
#define CP_COMMIT() asm volatile("cp.async.commit_group;\n" ::: "memory")
#define CP_WAIT1()  asm volatile("cp.async.wait_group 1;\n" ::: "memory")

__device__ __forceinline__ void ldmx4(uint32_t* r, uint32_t addr) {
    asm volatile("ldmatrix.sync.aligned.m8n8.x4.shared.b16 {%0,%1,%2,%3}, [%4];"
                 : "=r"(r[0]), "=r"(r[1]), "=r"(r[2]), "=r"(r[3]) : "r"(addr));
}
__device__ __forceinline__ void mma16816(float* c, const uint32_t* a,
                                         uint32_t b0, uint32_t b1) {
    asm volatile(
        "mma.sync.aligned.m16n8k16.row.col.f32.f16.f16.f32 "
        "{%0,%1,%2,%3}, {%4,%5,%6,%7}, {%8,%9}, {%0,%1,%2,%3};"
        : "+f"(c[0]), "+f"(c[1]), "+f"(c[2]), "+f"(c[3])
        : "r"(a[0]), "r"(a[1]), "r"(a[2]), "r"(a[3]), "r"(b0), "r"(b1));
}

__device__ __forceinline__ unsigned pk2h(float a, float b) {
    __half2 t = __floats2half2_rn(a, b);
    return *reinterpret_cast<unsigned*>(&t);
}
__device__ __forceinline__ void store_cast4h(__half* h, size_t i4,
                                             float a0, float a1, float a2, float a3) {
    reinterpret_cast<uint2*>(h)[i4] = make_uint2(pk2h(a0, a1), pk2h(a2, a3));
}

// ---------------------------------------------------------------------------
// weight cast: all four fp32 [N,K] weights -> fp16, one launch
// ---------------------------------------------------------------------------
__global__ void wcast4_kernel(const float* __restrict__ W0, const float* __restrict__ W1,
                              const float* __restrict__ W2, const float* __restrict__ W3,
                              __half* __restrict__ out) {
    const int j = blockIdx.y;
    const float* W = (j == 0) ? W0 : (j == 1) ? W1 : (j == 2) ? W2 : W3;
    int i = blockIdx.x * blockDim.x + threadIdx.x;
    if (i >= WN / 4) return;
    float4 w = reinterpret_cast<const float4*>(W)[i];
    store_cast4h(out + (size_t)j * WN, i, w.x, w.y, w.z, w.w);
}

// ---------------------------------------------------------------------------
// fused time-shift mix -> xk, xv, xr (fp16)
// ---------------------------------------------------------------------------
__global__ void mix_kernel(const float* __restrict__ x,
                           const float* __restrict__ mk,
                           const float* __restrict__ mv,
                           const float* __restrict__ mr,
                           __half* __restrict__ x3) {
    int i = blockIdx.x * blockDim.x + threadIdx.x;     // float4 idx
    if (i >= NELEM / 4) return;
    const int c4 = i & (NC / 4 - 1);
    const int t  = (i >> 8) & (NT - 1);

    float4 xc = reinterpret_cast<const float4*>(x)[i];
    float4 xp = (t == 0) ? make_float4(0.f, 0.f, 0.f, 0.f)
                         : reinterpret_cast<const float4*>(x)[i - NC / 4];
    float4 k4 = reinterpret_cast<const float4*>(mk)[c4];
    float4 v4 = reinterpret_cast<const float4*>(mv)[c4];
    float4 r4 = reinterpret_cast<const float4*>(mr)[c4];

    float dx0 = xc.x - xp.x, dx1 = xc.y - xp.y, dx2 = xc.z - xp.z, dx3 = xc.w - xp.w;

    store_cast4h(x3, i, fmaf(k4.x, dx0, xp.x), fmaf(k4.y, dx1, xp.y),
                        fmaf(k4.z, dx2, xp.z), fmaf(k4.w, dx3, xp.w));
    store_cast4h(x3 + NELEM, i, fmaf(v4.x, dx0, xp.x), fmaf(v4.y, dx1, xp.y),
                                fmaf(v4.z, dx2, xp.z), fmaf(v4.w, dx3, xp.w));
    store_cast4h(x3 + 2 * (size_t)NELEM, i,
                 fmaf(r4.x, dx0, xp.x), fmaf(r4.y, dx1, xp.y),
                 fmaf(r4.z, dx2, xp.z), fmaf(r4.w, dx3, xp.w));
}

// ---------------------------------------------------------------------------
// single-pass fp16 mma.sync GEMM: C[m,n] = sum_k A[m,k] * W[n,k]
// CTA tile 128x128x32, 8 warps (64x32 each), 3-stage cp.async pipeline,
// next-chunk loads issued before compute. blockIdx.z selects the job
// (A/W/C advance by the given strides). 2 CTAs/SM.
// ---------------------------------------------------------------------------
constexpr int LDT = 40;                    // padded smem row stride (halves)
constexpr int TILE_ELE = 128 * LDT;        // 5120 elems = 10240 B
constexpr int NSTAGE = 3;
constexpr int KCH = NC / 32;               // 32 chunks
constexpr int GEMM_SMEM = NSTAGE * 2 * TILE_ELE * 2;   // 61440 B

template<typename OutT>
__global__ void __launch_bounds__(256, 2)
gemm_h(const __half* __restrict__ Ab, const __half* __restrict__ Wb,
       OutT* __restrict__ Cb, size_t strideA, size_t strideW, size_t strideC) {
    extern __shared__ __half smem[];
    const uint32_t sb = smem_u32(smem);
    const int tid = threadIdx.x;
    const int lane = tid & 31;
    const int wid = tid >> 5;
    const int wm = wid & 1;          // M dir (64 rows)
    const int wn = wid >> 1;         // N dir (32 cols)
    const int nTile = blockIdx.x, mTile = blockIdx.y, job = blockIdx.z;

    const char* gA = (const char*)(Ab + job * strideA + (size_t)mTile * 128 * NC);
    const char* gW = (const char*)(Wb + job * strideW + (size_t)nTile * 128 * NC);
    OutT* C = Cb + job * strideC;

    // loader: per tile 512 x 16B; u = i*256 + tid -> row=u>>2, col=(u&3)*8
    auto load_chunk = [&](int c, int s) {
        uint32_t st = sb + (uint32_t)s * 2 * TILE_ELE * 2;
        #pragma unroll
        for (int i = 0; i < 2; i++) {
            int u = i * 256 + tid;
            int row = u >> 2, col = (u & 3) * 8;
            uint32_t so = (uint32_t)(row * LDT + col) * 2;
            size_t go = (size_t)row * 2048 + (size_t)(c * 32 + col) * 2;
            cp16(st + so, gA + go);
            cp16(st + TILE_ELE * 2 + so, gW + go);
        }
        CP_COMMIT();
    };

    load_chunk(0, 0);
    load_chunk(1, 1);

    float acc[4][4][4];
    #pragma unroll
    for (int mt = 0; mt < 4; mt++)
        #pragma unroll
        for (int nt = 0; nt < 4; nt++)
            #pragma unroll
            for (int q = 0; q < 4; q++) acc[mt][nt][q] = 0.f;

    const int lrow = lane & 15;
    const int lcol = (lane >> 4) * 8;

    for (int c = 0; c < KCH; c++) {
        const int s = c % NSTAGE;
        CP_WAIT1();
        __syncthreads();
        if (c + 2 < KCH) load_chunk(c + 2, (c + 2) % NSTAGE);
        else CP_COMMIT();

        const uint32_t st = sb + (uint32_t)s * 2 * TILE_ELE * 2;
        #pragma unroll
        for (int ks = 0; ks < 2; ks++) {
            const int kc = ks * 16 + lcol;
            uint32_t a[4][4], b[2][4];
            #pragma unroll
            for (int mt = 0; mt < 4; mt++)
                ldmx4(a[mt], st + (uint32_t)((wm * 64 + mt * 16 + lrow) * LDT + kc) * 2);
            #pragma unroll
            for (int pr = 0; pr < 2; pr++)
                ldmx4(b[pr], st + TILE_ELE * 2 +
                             (uint32_t)((wn * 32 + pr * 16 + lrow) * LDT + kc) * 2);
            #pragma unroll
            for (int mt = 0; mt < 4; mt++)
                #pragma unroll
                for (int nt = 0; nt < 4; nt++) {
                    const int pr = nt >> 1, ix = nt & 1;
                    mma16816(acc[mt][nt], a[mt], b[pr][ix], b[pr][ix + 2]);
                }
        }
        __syncthreads();
    }

    // epilogue
    const int erow = mTile * 128 + wm * 64 + (lane >> 2);
    const int ecol = nTile * 128 + wn * 32 + (lane & 3) * 2;
    #pragma unroll
    for (int mt = 0; mt < 4; mt++) {
        #pragma unroll
        for (int nt = 0; nt < 4; nt++) {
            OutT* p0 = C + (size_t)(erow + mt * 16) * NC + ecol + nt * 8;
            OutT* p1 = C + (size_t)(erow + mt * 16 + 8) * NC + ecol + nt * 8;
            if (sizeof(OutT) == 4) {
                *reinterpret_cast<float2*>(p0) = make_float2(acc[mt][nt][0], acc[mt][nt][1]);
                *reinterpret_cast<float2*>(p1) = make_float2(acc[mt][nt][2], acc[mt][nt][3]);
            } else {
                *reinterpret_cast<unsigned*>(p0) = pk2h(acc[mt][nt][0], acc[mt][nt][1]);
                *reinterpret_cast<unsigned*>(p1) = pk2h(acc[mt][nt][2], acc[mt][nt][3]);
            }
        }
    }
}

// ---------------------------------------------------------------------------
// chunk-parallel WKV scan (3 passes); k/v/r fp16, math in fp32
// ---------------------------------------------------------------------------
__global__ void scan_p1(const __half* __restrict__ k, const __half* __restrict__ v,
                        const float* __restrict__ td,
                        float* __restrict__ Sa, float* __restrict__ Sb) {
    const int c = blockIdx.x * blockDim.x + threadIdx.x;
    const int b = blockIdx.y, g = blockIdx.z;
    const float p = __expf(-__expf(td[c]));
    size_t idx = ((size_t)b * NT + g * SL) * NC + c;
    float A = 0.f, Bb = 0.f;
    #pragma unroll 4
    for (int t = 0; t < SL; t++, idx += NC) {
        float ek = __expf(fminf(__half2float(k[idx]), 60.f));
        float kv = ek * __half2float(v[idx]);
        A  = fmaf(p, A, kv);
        Bb = fmaf(p, Bb, ek);
    }
    size_t o = ((size_t)g * NB + b) * NC + c;
    Sa[o] = A; Sb[o] = Bb;
}

__global__ void scan_p2(const float* __restrict__ td,
                        float* __restrict__ Sa, float* __restrict__ Sb) {
    const int c = blockIdx.x * blockDim.x + threadIdx.x;
    const int b = blockIdx.y;
    const float pl = __expf(-__expf(td[c]) * (float)SL);   // p^SL
    float A = 0.f, Bb = 0.f;
    for (int g = 0; g < SG; g++) {
        size_t o = ((size_t)g * NB + b) * NC + c;
        float ta = Sa[o], tb = Sb[o];
        Sa[o] = A; Sb[o] = Bb;                 // start state for chunk g
        A  = fmaf(pl, A, ta);
        Bb = fmaf(pl, Bb, tb);
    }
}

__global__ void scan_p3(const __half* __restrict__ k, const __half* __restrict__ v,
                        const __half* __restrict__ r, const float* __restrict__ td,
                        const float* __restrict__ tf,
                        const float* __restrict__ Sa, const float* __restrict__ Sb,
                        __half* __restrict__ y) {
    const int c = blockIdx.x * blockDim.x + threadIdx.x;
    const int b = blockIdx.y, g = blockIdx.z;
    const float p = __expf(-__expf(td[c]));
    const float u = __expf(tf[c]);
    size_t o = ((size_t)g * NB + b) * NC + c;
    float A = Sa[o], Bb = Sb[o];
    size_t idx = ((size_t)b * NT + g * SL) * NC + c;
    #pragma unroll 2
    for (int t = 0; t < SL; t++, idx += NC) {
        float ek = __expf(fminf(__half2float(k[idx]), 60.f));
        float kv = ek * __half2float(v[idx]);
        float num = fmaf(u, kv, A);
        float den = fmaf(u, ek, Bb) + 1e-9f;
        float sig = 1.f / (1.f + __expf(-__half2float(r[idx])));
        y[idx] = __float2half_rn(sig * num / den);
        A  = fmaf(p, A, kv);
        Bb = fmaf(p, Bb, ek);
    }
}

// ---------------------------------------------------------------------------
// launch
// ---------------------------------------------------------------------------
extern "C" void kernel_launch(void* const* d_in, const int* in_sizes, int n_in,
                              void* d_out, int out_size) {
    const float* x  = (const float*)d_in[0];
    const float* td = (const float*)d_in[1];
    const float* tf = (const float*)d_in[2];
    const float* mk = (const float*)d_in[3];
    const float* mv = (const float*)d_in[4];
    const float* mr = (const float*)d_in[5];
    const float* Wk = (const float*)d_in[6];
    const float* Wv = (const float*)d_in[7];
    const float* Wr = (const float*)d_in[8];
    const float* Wo = (const float*)d_in[9];
    float* out = (float*)d_out;

    __half *x3, *kvr, *w;
    float *Sa, *Sb;
    cudaGetSymbolAddress((void**)&x3, g_x3);
    cudaGetSymbolAddress((void**)&kvr, g_kvr);
    cudaGetSymbolAddress((void**)&w, g_w);
    cudaGetSymbolAddress((void**)&Sa, g_Sa);
    cudaGetSymbolAddress((void**)&Sb, g_Sb);

    cudaFuncSetAttribute(gemm_h<__half>,
                         cudaFuncAttributeMaxDynamicSharedMemorySize, GEMM_SMEM);
    cudaFuncSetAttribute(gemm_h<float>,
                         cudaFuncAttributeMaxDynamicSharedMemorySize, GEMM_SMEM);

    // 1) weight casts (one launch)
    wcast4_kernel<<<dim3(WN / 4 / 256, 4), 256>>>(Wk, Wv, Wr, Wo, w);

    // 2) fused time-shift mix -> xk|xv|xr fp16
    mix_kernel<<<NELEM / 4 / 256, 256>>>(x, mk, mv, mr, x3);

    // 3) k/v/r projections, one merged launch (z = job)
    gemm_h<__half><<<dim3(NC / 128, MG / 128, 3), 256, GEMM_SMEM>>>(
        x3, w, kvr, (size_t)NELEM, (size_t)WN, (size_t)NELEM);

    // 4) chunk-parallel WKV scan; y (rwkv) into x3 slice 0 (reuse)
    const __half* kb = kvr;
    const __half* vb = kvr + (size_t)NELEM;
    const __half* rb = kvr + 2 * (size_t)NELEM;
    scan_p1<<<dim3(NC / 256, NB, SG), 256>>>(kb, vb, td, Sa, Sb);
    scan_p2<<<dim3(NC / 256, NB), 256>>>(td, Sa, Sb);
    scan_p3<<<dim3(NC / 256, NB, SG), 256>>>(kb, vb, rb, td, tf, Sa, Sb, x3);

    // 5) output projection (fp32 out)
    gemm_h<float><<<dim3(NC / 128, MG / 128, 1), 256, GEMM_SMEM>>>(
        x3, w + 3 * (size_t)WN, out, 0, 0, 0);
}

// round 9
// speedup vs baseline: 7.3859x; 1.4795x over previous
#include <cuda_runtime.h>
#include <cuda_fp16.h>
#include <cstdint>
#include <math.h>

// Problem dims (fixed)
constexpr int NB = 8;
constexpr int NT = 1024;
constexpr int NC = 1024;
constexpr int NELEM = NB * NT * NC;   // 8M
constexpr int MG = NB * NT;           // 8192 GEMM rows
constexpr int WN = NC * NC;

// scan chunking
constexpr int SG = 16;                // chunks along T
constexpr int SL = NT / SG;           // 64 steps per chunk

// ---------------- scratch (device globals; no runtime alloc) ----------------
__device__ __half g_x3[3 * NELEM];    // xk | xv | xr  (slice 0 reused for rwkv y)
__device__ __half g_kvr[3 * NELEM];   // k | v | r
__device__ __half g_w[4 * WN];        // wk | wv | wr | wo
__device__ float g_Sa[SG * NB * NC], g_Sb[SG * NB * NC];

// ---------------- helpers ----------------
__device__ __forceinline__ uint32_t smem_u32(const void* p) {
    uint32_t a;
    asm("{ .reg .u64 t; cvta.to.shared.u64 t, %1; cvt.u32.u64 %0, t; }"
        : "=r"(a) : "l"(p));
    return a;
}
__device__ __forceinline__ void cp16(uint32_t s, const void* g) {
    asm volatile("cp.async.cg.shared.global [%0], [%1], 16;\n" :: "r"(s), "l"(g));
}
#define CP_COMMIT() asm volatile("cp.async.commit_group;\n" ::: "memory")
#define CP_WAIT1()  asm volatile("cp.async.wait_group 1;\n" ::: "memory")

__device__ __forceinline__ void ldmx4(uint32_t* r, uint32_t addr) {
    asm volatile("ldmatrix.sync.aligned.m8n8.x4.shared.b16 {%0,%1,%2,%3}, [%4];"
                 : "=r"(r[0]), "=r"(r[1]), "=r"(r[2]), "=r"(r[3]) : "r"(addr));
}
__device__ __forceinline__ void mma16816(float* c, const uint32_t* a,
                                         uint32_t b0, uint32_t b1) {
    asm volatile(
        "mma.sync.aligned.m16n8k16.row.col.f32.f16.f16.f32 "
        "{%0,%1,%2,%3}, {%4,%5,%6,%7}, {%8,%9}, {%0,%1,%2,%3};"
        : "+f"(c[0]), "+f"(c[1]), "+f"(c[2]), "+f"(c[3])
        : "r"(a[0]), "r"(a[1]), "r"(a[2]), "r"(a[3]), "r"(b0), "r"(b1));
}

__device__ __forceinline__ unsigned pk2h(float a, float b) {
    __half2 t = __floats2half2_rn(a, b);
    return *reinterpret_cast<unsigned*>(&t);
}
__device__ __forceinline__ void store_cast4h(__half* h, size_t i4,
                                             float a0, float a1, float a2, float a3) {
    reinterpret_cast<uint2*>(h)[i4] = make_uint2(pk2h(a0, a1), pk2h(a2, a3));
}

// ---------------------------------------------------------------------------
// weight cast: all four fp32 [N,K] weights -> fp16, one launch
// ---------------------------------------------------------------------------
__global__ void wcast4_kernel(const float* __restrict__ W0, const float* __restrict__ W1,
                              const float* __restrict__ W2, const float* __restrict__ W3,
                              __half* __restrict__ out) {
    const int j = blockIdx.y;
    const float* W = (j == 0) ? W0 : (j == 1) ? W1 : (j == 2) ? W2 : W3;
    int i = blockIdx.x * blockDim.x + threadIdx.x;
    if (i >= WN / 4) return;
    float4 w = reinterpret_cast<const float4*>(W)[i];
    store_cast4h(out + (size_t)j * WN, i, w.x, w.y, w.z, w.w);
}

// ---------------------------------------------------------------------------
// fused time-shift mix -> xk, xv, xr (fp16)
// ---------------------------------------------------------------------------
__global__ void mix_kernel(const float* __restrict__ x,
                           const float* __restrict__ mk,
                           const float* __restrict__ mv,
                           const float* __restrict__ mr,
                           __half* __restrict__ x3) {
    int i = blockIdx.x * blockDim.x + threadIdx.x;     // float4 idx
    if (i >= NELEM / 4) return;
    const int c4 = i & (NC / 4 - 1);
    const int t  = (i >> 8) & (NT - 1);

    float4 xc = reinterpret_cast<const float4*>(x)[i];
    float4 xp = (t == 0) ? make_float4(0.f, 0.f, 0.f, 0.f)
                         : reinterpret_cast<const float4*>(x)[i - NC / 4];
    float4 k4 = reinterpret_cast<const float4*>(mk)[c4];
    float4 v4 = reinterpret_cast<const float4*>(mv)[c4];
    float4 r4 = reinterpret_cast<const float4*>(mr)[c4];

    float dx0 = xc.x - xp.x, dx1 = xc.y - xp.y, dx2 = xc.z - xp.z, dx3 = xc.w - xp.w;

    store_cast4h(x3, i, fmaf(k4.x, dx0, xp.x), fmaf(k4.y, dx1, xp.y),
                        fmaf(k4.z, dx2, xp.z), fmaf(k4.w, dx3, xp.w));
    store_cast4h(x3 + NELEM, i, fmaf(v4.x, dx0, xp.x), fmaf(v4.y, dx1, xp.y),
                                fmaf(v4.z, dx2, xp.z), fmaf(v4.w, dx3, xp.w));
    store_cast4h(x3 + 2 * (size_t)NELEM, i,
                 fmaf(r4.x, dx0, xp.x), fmaf(r4.y, dx1, xp.y),
                 fmaf(r4.z, dx2, xp.z), fmaf(r4.w, dx3, xp.w));
}

// ---------------------------------------------------------------------------
// single-pass fp16 mma.sync GEMM: C[m,n] = sum_k A[m,k] * W[n,k]
// CTA tile 128x128x32, 4 warps (64x64 each), 3-stage cp.async pipeline.
// blockIdx.z selects the job. 2 CTAs/SM.
// ---------------------------------------------------------------------------
constexpr int LDT = 40;                    // padded smem row stride (halves)
constexpr int TILE_ELE = 128 * LDT;        // 5120 elems = 10240 B
constexpr int NSTAGE = 3;
constexpr int KCH = NC / 32;               // 32 chunks
constexpr int GEMM_SMEM = NSTAGE * 2 * TILE_ELE * 2;   // 61440 B

template<typename OutT>
__global__ void __launch_bounds__(128, 2)
gemm_h(const __half* __restrict__ Ab, const __half* __restrict__ Wb,
       OutT* __restrict__ Cb, size_t strideA, size_t strideW, size_t strideC) {
    extern __shared__ __half smem[];
    const uint32_t sb = smem_u32(smem);
    const int tid = threadIdx.x;
    const int lane = tid & 31;
    const int wid = tid >> 5;        // 0..3
    const int wm = wid & 1;          // M dir (64 rows)
    const int wn = wid >> 1;         // N dir (64 cols)
    const int nTile = blockIdx.x, mTile = blockIdx.y, job = blockIdx.z;

    const char* gA = (const char*)(Ab + job * strideA + (size_t)mTile * 128 * NC);
    const char* gW = (const char*)(Wb + job * strideW + (size_t)nTile * 128 * NC);
    OutT* C = Cb + job * strideC;

    // loader: per tile 512 x 16B units; u = i*128 + tid -> row=u>>2, col=(u&3)*8
    auto load_chunk = [&](int c, int s) {
        uint32_t st = sb + (uint32_t)s * 2 * TILE_ELE * 2;
        #pragma unroll
        for (int i = 0; i < 4; i++) {
            int u = i * 128 + tid;
            int row = u >> 2, col = (u & 3) * 8;
            uint32_t so = (uint32_t)(row * LDT + col) * 2;
            size_t go = (size_t)row * 2048 + (size_t)(c * 32 + col) * 2;
            cp16(st + so, gA + go);
            cp16(st + TILE_ELE * 2 + so, gW + go);
        }
        CP_COMMIT();
    };

    load_chunk(0, 0);
    load_chunk(1, 1);

    float acc[4][8][4];
    #pragma unroll
    for (int mt = 0; mt < 4; mt++)
        #pragma unroll
        for (int nt = 0; nt < 8; nt++)
            #pragma unroll
            for (int q = 0; q < 4; q++) acc[mt][nt][q] = 0.f;

    const int lrow = lane & 15;
    const int lcol = (lane >> 4) * 8;

    for (int c = 0; c < KCH; c++) {
        const int s = c % NSTAGE;
        CP_WAIT1();
        __syncthreads();
        if (c + 2 < KCH) load_chunk(c + 2, (c + 2) % NSTAGE);
        else CP_COMMIT();

        const uint32_t st = sb + (uint32_t)s * 2 * TILE_ELE * 2;
        #pragma unroll
        for (int ks = 0; ks < 2; ks++) {
            const int kc = ks * 16 + lcol;
            uint32_t a[4][4], b[4][4];
            #pragma unroll
            for (int mt = 0; mt < 4; mt++)
                ldmx4(a[mt], st + (uint32_t)((wm * 64 + mt * 16 + lrow) * LDT + kc) * 2);
            #pragma unroll
            for (int pr = 0; pr < 4; pr++)
                ldmx4(b[pr], st + TILE_ELE * 2 +
                             (uint32_t)((wn * 64 + pr * 16 + lrow) * LDT + kc) * 2);
            #pragma unroll
            for (int mt = 0; mt < 4; mt++)
                #pragma unroll
                for (int nt = 0; nt < 8; nt++) {
                    const int pr = nt >> 1, ix = nt & 1;
                    mma16816(acc[mt][nt], a[mt], b[pr][ix], b[pr][ix + 2]);
                }
        }
        __syncthreads();
    }

    // epilogue
    const int erow = mTile * 128 + wm * 64 + (lane >> 2);
    const int ecol = nTile * 128 + wn * 64 + (lane & 3) * 2;
    #pragma unroll
    for (int mt = 0; mt < 4; mt++) {
        #pragma unroll
        for (int nt = 0; nt < 8; nt++) {
            OutT* p0 = C + (size_t)(erow + mt * 16) * NC + ecol + nt * 8;
            OutT* p1 = C + (size_t)(erow + mt * 16 + 8) * NC + ecol + nt * 8;
            if (sizeof(OutT) == 4) {
                *reinterpret_cast<float2*>(p0) = make_float2(acc[mt][nt][0], acc[mt][nt][1]);
                *reinterpret_cast<float2*>(p1) = make_float2(acc[mt][nt][2], acc[mt][nt][3]);
            } else {
                *reinterpret_cast<unsigned*>(p0) = pk2h(acc[mt][nt][0], acc[mt][nt][1]);
                *reinterpret_cast<unsigned*>(p1) = pk2h(acc[mt][nt][2], acc[mt][nt][3]);
            }
        }
    }
}

// ---------------------------------------------------------------------------
// chunk-parallel WKV scan (3 passes); k/v/r fp16 (half2: 2 channels/thread)
// ---------------------------------------------------------------------------
__global__ void scan_p1(const __half2* __restrict__ k, const __half2* __restrict__ v,
                        const float* __restrict__ td,
                        float2* __restrict__ Sa, float2* __restrict__ Sb) {
    const int c2 = blockIdx.x * blockDim.x + threadIdx.x;  // 0..NC/2-1
    const int b = blockIdx.y, g = blockIdx.z;
    const float2 tdv = reinterpret_cast<const float2*>(td)[c2];
    const float px = __expf(-__expf(tdv.x));
    const float py = __expf(-__expf(tdv.y));

    size_t idx = ((size_t)b * NT + g * SL) * (NC / 2) + c2;
    float Ax = 0.f, Ay = 0.f, Bx = 0.f, By = 0.f;
    #pragma unroll 8
    for (int t = 0; t < SL; t++, idx += NC / 2) {
        float2 kf = __half22float2(k[idx]);
        float2 vf = __half22float2(v[idx]);
        float ekx = __expf(fminf(kf.x, 60.f));
        float eky = __expf(fminf(kf.y, 60.f));
        Ax = fmaf(px, Ax, ekx * vf.x);
        Ay = fmaf(py, Ay, eky * vf.y);
        Bx = fmaf(px, Bx, ekx);
        By = fmaf(py, By, eky);
    }
    size_t o = ((size_t)g * NB + b) * (NC / 2) + c2;
    Sa[o] = make_float2(Ax, Ay);
    Sb[o] = make_float2(Bx, By);
}

__global__ void scan_p2(const float* __restrict__ td,
                        float* __restrict__ Sa, float* __restrict__ Sb) {
    const int c = blockIdx.x * blockDim.x + threadIdx.x;
    const int b = blockIdx.y;
    const float pl = __expf(-__expf(td[c]) * (float)SL);   // p^SL
    float A = 0.f, Bb = 0.f;
    for (int g = 0; g < SG; g++) {
        size_t o = ((size_t)g * NB + b) * NC + c;
        float ta = Sa[o], tb = Sb[o];
        Sa[o] = A; Sb[o] = Bb;                 // start state for chunk g
        A  = fmaf(pl, A, ta);
        Bb = fmaf(pl, Bb, tb);
    }
}

__global__ void scan_p3(const __half2* __restrict__ k, const __half2* __restrict__ v,
                        const __half2* __restrict__ r, const float* __restrict__ td,
                        const float* __restrict__ tf,
                        const float2* __restrict__ Sa, const float2* __restrict__ Sb,
                        __half2* __restrict__ y) {
    const int c2 = blockIdx.x * blockDim.x + threadIdx.x;
    const int b = blockIdx.y, g = blockIdx.z;
    const float2 tdv = reinterpret_cast<const float2*>(td)[c2];
    const float2 tfv = reinterpret_cast<const float2*>(tf)[c2];
    const float px = __expf(-__expf(tdv.x));
    const float py = __expf(-__expf(tdv.y));
    const float ux = __expf(tfv.x);
    const float uy = __expf(tfv.y);

    size_t o = ((size_t)g * NB + b) * (NC / 2) + c2;
    float2 Af = Sa[o], Bf = Sb[o];
    float Ax = Af.x, Ay = Af.y, Bx = Bf.x, By = Bf.y;

    size_t idx = ((size_t)b * NT + g * SL) * (NC / 2) + c2;
    #pragma unroll 4
    for (int t = 0; t < SL; t++, idx += NC / 2) {
        float2 kf = __half22float2(k[idx]);
        float2 vf = __half22float2(v[idx]);
        float2 rf = __half22float2(r[idx]);
        float ekx = __expf(fminf(kf.x, 60.f));
        float eky = __expf(fminf(kf.y, 60.f));
        float kvx = ekx * vf.x, kvy = eky * vf.y;
        float nx = fmaf(ux, kvx, Ax), ny = fmaf(uy, kvy, Ay);
        float dx = fmaf(ux, ekx, Bx) + 1e-9f, dy = fmaf(uy, eky, By) + 1e-9f;
        float sx = 1.f / (1.f + __expf(-rf.x));
        float sy = 1.f / (1.f + __expf(-rf.y));
        y[idx] = __floats2half2_rn(sx * nx / dx, sy * ny / dy);
        Ax = fmaf(px, Ax, kvx);  Ay = fmaf(py, Ay, kvy);
        Bx = fmaf(px, Bx, ekx);  By = fmaf(py, By, eky);
    }
}

// ---------------------------------------------------------------------------
// launch
// ---------------------------------------------------------------------------
extern "C" void kernel_launch(void* const* d_in, const int* in_sizes, int n_in,
                              void* d_out, int out_size) {
    const float* x  = (const float*)d_in[0];
    const float* td = (const float*)d_in[1];
    const float* tf = (const float*)d_in[2];
    const float* mk = (const float*)d_in[3];
    const float* mv = (const float*)d_in[4];
    const float* mr = (const float*)d_in[5];
    const float* Wk = (const float*)d_in[6];
    const float* Wv = (const float*)d_in[7];
    const float* Wr = (const float*)d_in[8];
    const float* Wo = (const float*)d_in[9];
    float* out = (float*)d_out;

    __half *x3, *kvr, *w;
    float *Sa, *Sb;
    cudaGetSymbolAddress((void**)&x3, g_x3);
    cudaGetSymbolAddress((void**)&kvr, g_kvr);
    cudaGetSymbolAddress((void**)&w, g_w);
    cudaGetSymbolAddress((void**)&Sa, g_Sa);
    cudaGetSymbolAddress((void**)&Sb, g_Sb);

    cudaFuncSetAttribute(gemm_h<__half>,
                         cudaFuncAttributeMaxDynamicSharedMemorySize, GEMM_SMEM);
    cudaFuncSetAttribute(gemm_h<float>,
                         cudaFuncAttributeMaxDynamicSharedMemorySize, GEMM_SMEM);

    // 1) weight casts (one launch)
    wcast4_kernel<<<dim3(WN / 4 / 256, 4), 256>>>(Wk, Wv, Wr, Wo, w);

    // 2) fused time-shift mix -> xk|xv|xr fp16
    mix_kernel<<<NELEM / 4 / 256, 256>>>(x, mk, mv, mr, x3);

    // 3) k/v/r projections, one merged launch (z = job)
    gemm_h<__half><<<dim3(NC / 128, MG / 128, 3), 128, GEMM_SMEM>>>(
        x3, w, kvr, (size_t)NELEM, (size_t)WN, (size_t)NELEM);

    // 4) chunk-parallel WKV scan; y (rwkv) into x3 slice 0 (reuse)
    const __half2* kb = (const __half2*)kvr;
    const __half2* vb = (const __half2*)(kvr + (size_t)NELEM);
    const __half2* rb = (const __half2*)(kvr + 2 * (size_t)NELEM);
    scan_p1<<<dim3(NC / 2 / 128, NB, SG), 128>>>(kb, vb, td,
                                                 (float2*)Sa, (float2*)Sb);
    scan_p2<<<dim3(NC / 256, NB), 256>>>(td, Sa, Sb);
    scan_p3<<<dim3(NC / 2 / 128, NB, SG), 128>>>(kb, vb, rb, td, tf,
                                                 (const float2*)Sa, (const float2*)Sb,
                                                 (__half2*)x3);

    // 5) output projection (fp32 out)
    gemm_h<float><<<dim3(NC / 128, MG / 128, 1), 128, GEMM_SMEM>>>(
        x3, w + 3 * (size_t)WN, out, 0, 0, 0);
}

// round 10
// speedup vs baseline: 8.5897x; 1.1630x over previous
#include <cuda_runtime.h>
#include <cuda_fp16.h>
#include <cstdint>
#include <math.h>

// Problem dims (fixed)
constexpr int NB = 8;
constexpr int NT = 1024;
constexpr int NC = 1024;
constexpr int NELEM = NB * NT * NC;   // 8M
constexpr int MG = NB * NT;           // 8192 GEMM rows
constexpr int WN = NC * NC;

// scan chunking
constexpr int SG = 32;                // chunks along T
constexpr int SL = NT / SG;           // 32 steps per chunk

// ---------------- scratch (device globals; no runtime alloc) ----------------
__device__ __half g_x3[3 * NELEM];    // xk | xv | xr  (slice 0 reused for rwkv y)
__device__ __half g_kvr[3 * NELEM];   // k | v | r
__device__ __half g_w[4 * WN];        // wk | wv | wr | wo
__device__ float g_Sa[SG * NB * NC], g_Sb[SG * NB * NC];

// ---------------- helpers ----------------
__device__ __forceinline__ uint32_t smem_u32(const void* p) {
    uint32_t a;
    asm("{ .reg .u64 t; cvta.to.shared.u64 t, %1; cvt.u32.u64 %0, t; }"
        : "=r"(a) : "l"(p));
    return a;
}
__device__ __forceinline__ void cp16(uint32_t s, const void* g) {
    asm volatile("cp.async.cg.shared.global [%0], [%1], 16;\n" :: "r"(s), "l"(g));
}
#define CP_COMMIT() asm volatile("cp.async.commit_group;\n" ::: "memory")
#define CP_WAIT1()  asm volatile("cp.async.wait_group 1;\n" ::: "memory")

__device__ __forceinline__ void ldmx4(uint32_t* r, uint32_t addr) {
    asm volatile("ldmatrix.sync.aligned.m8n8.x4.shared.b16 {%0,%1,%2,%3}, [%4];"
                 : "=r"(r[0]), "=r"(r[1]), "=r"(r[2]), "=r"(r[3]) : "r"(addr));
}
__device__ __forceinline__ void mma16816(float* c, const uint32_t* a,
                                         uint32_t b0, uint32_t b1) {
    asm volatile(
        "mma.sync.aligned.m16n8k16.row.col.f32.f16.f16.f32 "
        "{%0,%1,%2,%3}, {%4,%5,%6,%7}, {%8,%9}, {%0,%1,%2,%3};"
        : "+f"(c[0]), "+f"(c[1]), "+f"(c[2]), "+f"(c[3])
        : "r"(a[0]), "r"(a[1]), "r"(a[2]), "r"(a[3]), "r"(b0), "r"(b1));
}

__device__ __forceinline__ unsigned pk2h(float a, float b) {
    __half2 t = __floats2half2_rn(a, b);
    return *reinterpret_cast<unsigned*>(&t);
}
__device__ __forceinline__ void store_cast4h(__half* h, size_t i4,
                                             float a0, float a1, float a2, float a3) {
    reinterpret_cast<uint2*>(h)[i4] = make_uint2(pk2h(a0, a1), pk2h(a2, a3));
}

// ---------------------------------------------------------------------------
// weight cast: all four fp32 [N,K] weights -> fp16, one launch
// ---------------------------------------------------------------------------
__global__ void wcast4_kernel(const float* __restrict__ W0, const float* __restrict__ W1,
                              const float* __restrict__ W2, const float* __restrict__ W3,
                              __half* __restrict__ out) {
    const int j = blockIdx.y;
    const float* W = (j == 0) ? W0 : (j == 1) ? W1 : (j == 2) ? W2 : W3;
    int i = blockIdx.x * blockDim.x + threadIdx.x;
    if (i >= WN / 4) return;
    float4 w = reinterpret_cast<const float4*>(W)[i];
    store_cast4h(out + (size_t)j * WN, i, w.x, w.y, w.z, w.w);
}

// ---------------------------------------------------------------------------
// fused time-shift mix -> xk, xv, xr (fp16)
// ---------------------------------------------------------------------------
__global__ void mix_kernel(const float* __restrict__ x,
                           const float* __restrict__ mk,
                           const float* __restrict__ mv,
                           const float* __restrict__ mr,
                           __half* __restrict__ x3) {
    int i = blockIdx.x * blockDim.x + threadIdx.x;     // float4 idx
    if (i >= NELEM / 4) return;
    const int c4 = i & (NC / 4 - 1);
    const int t  = (i >> 8) & (NT - 1);

    float4 xc = reinterpret_cast<const float4*>(x)[i];
    float4 xp = (t == 0) ? make_float4(0.f, 0.f, 0.f, 0.f)
                         : reinterpret_cast<const float4*>(x)[i - NC / 4];
    float4 k4 = reinterpret_cast<const float4*>(mk)[c4];
    float4 v4 = reinterpret_cast<const float4*>(mv)[c4];
    float4 r4 = reinterpret_cast<const float4*>(mr)[c4];

    float dx0 = xc.x - xp.x, dx1 = xc.y - xp.y, dx2 = xc.z - xp.z, dx3 = xc.w - xp.w;

    store_cast4h(x3, i, fmaf(k4.x, dx0, xp.x), fmaf(k4.y, dx1, xp.y),
                        fmaf(k4.z, dx2, xp.z), fmaf(k4.w, dx3, xp.w));
    store_cast4h(x3 + NELEM, i, fmaf(v4.x, dx0, xp.x), fmaf(v4.y, dx1, xp.y),
                                fmaf(v4.z, dx2, xp.z), fmaf(v4.w, dx3, xp.w));
    store_cast4h(x3 + 2 * (size_t)NELEM, i,
                 fmaf(r4.x, dx0, xp.x), fmaf(r4.y, dx1, xp.y),
                 fmaf(r4.z, dx2, xp.z), fmaf(r4.w, dx3, xp.w));
}

// ---------------------------------------------------------------------------
// single-pass fp16 mma.sync GEMM: C[m,n] = sum_k A[m,k] * W[n,k]
// CTA tile 128x128x64, 4 warps (64x64 each), 3-stage cp.async pipeline,
// K-chunk 64 (4 ks-steps per barrier pair). blockIdx.z = job. 2 CTAs/SM.
// ---------------------------------------------------------------------------
constexpr int LDT = 72;                    // padded smem row stride (halves)
constexpr int TILE_ELE = 128 * LDT;        // 9216 halves = 18432 B
constexpr int NSTAGE = 3;
constexpr int KCH = NC / 64;               // 16 chunks
constexpr int GEMM_SMEM = NSTAGE * 2 * TILE_ELE * 2;   // 110592 B

template<typename OutT>
__global__ void __launch_bounds__(128, 2)
gemm_h(const __half* __restrict__ Ab, const __half* __restrict__ Wb,
       OutT* __restrict__ Cb, size_t strideA, size_t strideW, size_t strideC) {
    extern __shared__ __half smem[];
    const uint32_t sb = smem_u32(smem);
    const int tid = threadIdx.x;
    const int lane = tid & 31;
    const int wid = tid >> 5;        // 0..3
    const int wm = wid & 1;          // M dir (64 rows)
    const int wn = wid >> 1;         // N dir (64 cols)
    const int nTile = blockIdx.x, mTile = blockIdx.y, job = blockIdx.z;

    const char* gA = (const char*)(Ab + job * strideA + (size_t)mTile * 128 * NC);
    const char* gW = (const char*)(Wb + job * strideW + (size_t)nTile * 128 * NC);
    OutT* C = Cb + job * strideC;

    // loader: per tile 1024 x 16B units; u = i*128 + tid -> row=u>>3, colu=u&7
    auto load_chunk = [&](int c, int s) {
        uint32_t st = sb + (uint32_t)s * 2 * TILE_ELE * 2;
        #pragma unroll
        for (int i = 0; i < 8; i++) {
            int u = i * 128 + tid;
            int row = u >> 3, colu = u & 7;
            uint32_t so = (uint32_t)(row * LDT + colu * 8) * 2;
            size_t go = (size_t)row * 2048 + (size_t)(c * 64 + colu * 8) * 2;
            cp16(st + so, gA + go);
            cp16(st + TILE_ELE * 2 + so, gW + go);
        }
        CP_COMMIT();
    };

    load_chunk(0, 0);
    load_chunk(1, 1);

    float acc[4][8][4];
    #pragma unroll
    for (int mt = 0; mt < 4; mt++)
        #pragma unroll
        for (int nt = 0; nt < 8; nt++)
            #pragma unroll
            for (int q = 0; q < 4; q++) acc[mt][nt][q] = 0.f;

    const int lrow = lane & 15;
    const int lcol = (lane >> 4) * 8;

    for (int c = 0; c < KCH; c++) {
        const int s = c % NSTAGE;
        CP_WAIT1();
        __syncthreads();
        if (c + 2 < KCH) load_chunk(c + 2, (c + 2) % NSTAGE);
        else CP_COMMIT();

        const uint32_t st = sb + (uint32_t)s * 2 * TILE_ELE * 2;
        #pragma unroll
        for (int ks = 0; ks < 4; ks++) {
            const int kc = ks * 16 + lcol;
            uint32_t a[4][4], b[4][4];
            #pragma unroll
            for (int mt = 0; mt < 4; mt++)
                ldmx4(a[mt], st + (uint32_t)((wm * 64 + mt * 16 + lrow) * LDT + kc) * 2);
            #pragma unroll
            for (int pr = 0; pr < 4; pr++)
                ldmx4(b[pr], st + TILE_ELE * 2 +
                             (uint32_t)((wn * 64 + pr * 16 + lrow) * LDT + kc) * 2);
            #pragma unroll
            for (int mt = 0; mt < 4; mt++)
                #pragma unroll
                for (int nt = 0; nt < 8; nt++) {
                    const int pr = nt >> 1, ix = nt & 1;
                    mma16816(acc[mt][nt], a[mt], b[pr][ix], b[pr][ix + 2]);
                }
        }
        __syncthreads();
    }

    // epilogue
    const int erow = mTile * 128 + wm * 64 + (lane >> 2);
    const int ecol = nTile * 128 + wn * 64 + (lane & 3) * 2;
    #pragma unroll
    for (int mt = 0; mt < 4; mt++) {
        #pragma unroll
        for (int nt = 0; nt < 8; nt++) {
            OutT* p0 = C + (size_t)(erow + mt * 16) * NC + ecol + nt * 8;
            OutT* p1 = C + (size_t)(erow + mt * 16 + 8) * NC + ecol + nt * 8;
            if (sizeof(OutT) == 4) {
                *reinterpret_cast<float2*>(p0) = make_float2(acc[mt][nt][0], acc[mt][nt][1]);
                *reinterpret_cast<float2*>(p1) = make_float2(acc[mt][nt][2], acc[mt][nt][3]);
            } else {
                *reinterpret_cast<unsigned*>(p0) = pk2h(acc[mt][nt][0], acc[mt][nt][1]);
                *reinterpret_cast<unsigned*>(p1) = pk2h(acc[mt][nt][2], acc[mt][nt][3]);
            }
        }
    }
}

// ---------------------------------------------------------------------------
// chunk-parallel WKV scan (3 passes); k/v/r fp16 (half2: 2 channels/thread)
// ---------------------------------------------------------------------------
__global__ void scan_p1(const __half2* __restrict__ k, const __half2* __restrict__ v,
                        const float* __restrict__ td,
                        float2* __restrict__ Sa, float2* __restrict__ Sb) {
    const int c2 = blockIdx.x * blockDim.x + threadIdx.x;  // 0..NC/2-1
    const int b = blockIdx.y, g = blockIdx.z;
    const float2 tdv = reinterpret_cast<const float2*>(td)[c2];
    const float px = __expf(-__expf(tdv.x));
    const float py = __expf(-__expf(tdv.y));

    size_t idx = ((size_t)b * NT + g * SL) * (NC / 2) + c2;
    float Ax = 0.f, Ay = 0.f, Bx = 0.f, By = 0.f;
    #pragma unroll 8
    for (int t = 0; t < SL; t++, idx += NC / 2) {
        float2 kf = __half22float2(k[idx]);
        float2 vf = __half22float2(v[idx]);
        float ekx = __expf(fminf(kf.x, 60.f));
        float eky = __expf(fminf(kf.y, 60.f));
        Ax = fmaf(px, Ax, ekx * vf.x);
        Ay = fmaf(py, Ay, eky * vf.y);
        Bx = fmaf(px, Bx, ekx);
        By = fmaf(py, By, eky);
    }
    size_t o = ((size_t)g * NB + b) * (NC / 2) + c2;
    Sa[o] = make_float2(Ax, Ay);
    Sb[o] = make_float2(Bx, By);
}

__global__ void scan_p2(const float* __restrict__ td,
                        float* __restrict__ Sa, float* __restrict__ Sb) {
    const int c = blockIdx.x * blockDim.x + threadIdx.x;
    const int b = blockIdx.y;
    const float pl = __expf(-__expf(td[c]) * (float)SL);   // p^SL
    float A = 0.f, Bb = 0.f;
    for (int g = 0; g < SG; g++) {
        size_t o = ((size_t)g * NB + b) * NC + c;
        float ta = Sa[o], tb = Sb[o];
        Sa[o] = A; Sb[o] = Bb;                 // start state for chunk g
        A  = fmaf(pl, A, ta);
        Bb = fmaf(pl, Bb, tb);
    }
}

__global__ void scan_p3(const __half2* __restrict__ k, const __half2* __restrict__ v,
                        const __half2* __restrict__ r, const float* __restrict__ td,
                        const float* __restrict__ tf,
                        const float2* __restrict__ Sa, const float2* __restrict__ Sb,
                        __half2* __restrict__ y) {
    const int c2 = blockIdx.x * blockDim.x + threadIdx.x;
    const int b = blockIdx.y, g = blockIdx.z;
    const float2 tdv = reinterpret_cast<const float2*>(td)[c2];
    const float2 tfv = reinterpret_cast<const float2*>(tf)[c2];
    const float px = __expf(-__expf(tdv.x));
    const float py = __expf(-__expf(tdv.y));
    const float ux = __expf(tfv.x);
    const float uy = __expf(tfv.y);

    size_t o = ((size_t)g * NB + b) * (NC / 2) + c2;
    float2 Af = Sa[o], Bf = Sb[o];
    float Ax = Af.x, Ay = Af.y, Bx = Bf.x, By = Bf.y;

    size_t idx = ((size_t)b * NT + g * SL) * (NC / 2) + c2;
    #pragma unroll 4
    for (int t = 0; t < SL; t++, idx += NC / 2) {
        float2 kf = __half22float2(k[idx]);
        float2 vf = __half22float2(v[idx]);
        float2 rf = __half22float2(r[idx]);
        float ekx = __expf(fminf(kf.x, 60.f));
        float eky = __expf(fminf(kf.y, 60.f));
        float kvx = ekx * vf.x, kvy = eky * vf.y;
        float nx = fmaf(ux, kvx, Ax), ny = fmaf(uy, kvy, Ay);
        float dx = fmaf(ux, ekx, Bx) + 1e-9f, dy = fmaf(uy, eky, By) + 1e-9f;
        float sx = 1.f / (1.f + __expf(-rf.x));
        float sy = 1.f / (1.f + __expf(-rf.y));
        y[idx] = __floats2half2_rn(sx * nx / dx, sy * ny / dy);
        Ax = fmaf(px, Ax, kvx);  Ay = fmaf(py, Ay, kvy);
        Bx = fmaf(px, Bx, ekx);  By = fmaf(py, By, eky);
    }
}

// ---------------------------------------------------------------------------
// launch
// ---------------------------------------------------------------------------
extern "C" void kernel_launch(void* const* d_in, const int* in_sizes, int n_in,
                              void* d_out, int out_size) {
    const float* x  = (const float*)d_in[0];
    const float* td = (const float*)d_in[1];
    const float* tf = (const float*)d_in[2];
    const float* mk = (const float*)d_in[3];
    const float* mv = (const float*)d_in[4];
    const float* mr = (const float*)d_in[5];
    const float* Wk = (const float*)d_in[6];
    const float* Wv = (const float*)d_in[7];
    const float* Wr = (const float*)d_in[8];
    const float* Wo = (const float*)d_in[9];
    float* out = (float*)d_out;

    __half *x3, *kvr, *w;
    float *Sa, *Sb;
    cudaGetSymbolAddress((void**)&x3, g_x3);
    cudaGetSymbolAddress((void**)&kvr, g_kvr);
    cudaGetSymbolAddress((void**)&w, g_w);
    cudaGetSymbolAddress((void**)&Sa, g_Sa);
    cudaGetSymbolAddress((void**)&Sb, g_Sb);

    cudaFuncSetAttribute(gemm_h<__half>,
                         cudaFuncAttributeMaxDynamicSharedMemorySize, GEMM_SMEM);
    cudaFuncSetAttribute(gemm_h<float>,
                         cudaFuncAttributeMaxDynamicSharedMemorySize, GEMM_SMEM);

    // 1) weight casts (one launch)
    wcast4_kernel<<<dim3(WN / 4 / 256, 4), 256>>>(Wk, Wv, Wr, Wo, w);

    // 2) fused time-shift mix -> xk|xv|xr fp16
    mix_kernel<<<NELEM / 4 / 256, 256>>>(x, mk, mv, mr, x3);

    // 3) k/v/r projections, one merged launch (z = job)
    gemm_h<__half><<<dim3(NC / 128, MG / 128, 3), 128, GEMM_SMEM>>>(
        x3, w, kvr, (size_t)NELEM, (size_t)WN, (size_t)NELEM);

    // 4) chunk-parallel WKV scan; y (rwkv) into x3 slice 0 (reuse)
    const __half2* kb = (const __half2*)kvr;
    const __half2* vb = (const __half2*)(kvr + (size_t)NELEM);
    const __half2* rb = (const __half2*)(kvr + 2 * (size_t)NELEM);
    scan_p1<<<dim3(NC / 2 / 128, NB, SG), 128>>>(kb, vb, td,
                                                 (float2*)Sa, (float2*)Sb);
    scan_p2<<<dim3(NC / 256, NB), 256>>>(td, Sa, Sb);
    scan_p3<<<dim3(NC / 2 / 128, NB, SG), 128>>>(kb, vb, rb, td, tf,
                                                 (const float2*)Sa, (const float2*)Sb,
                                                 (__half2*)x3);

    // 5) output projection (fp32 out)
    gemm_h<float><<<dim3(NC / 128, MG / 128, 1), 128, GEMM_SMEM>>>(
        x3, w + 3 * (size_t)WN, out, 0, 0, 0);
}